// round 6
// baseline (speedup 1.0000x reference)
#include <cuda_runtime.h>
#include <math.h>

// ---------------------------------------------------------------------------
// Problem constants
// ---------------------------------------------------------------------------
namespace {
constexpr int NB = 2, NS = 1024, NHID = 1024, NHEAD = 8, DHEAD = 128;
constexpr int NEXP = 8, NMI = 1024, NSI = 2048;
constexpr int NT = NB * NS;          // 2048 tokens
constexpr int NSLOT = 2 * NT;        // 4096 expert slots (top-2)

constexpr int PADK = 20;             // 16 + 4 pad, conflict-free (20g+t)%32

// small GEMM (PV only): 128x128, 4 stages
constexpr int BM = 128, BN = 128, BK = 16;
constexpr int STAGES = 4;
constexpr int SMEM_WORDS_HALF = STAGES * BM * PADK;
constexpr int SMEM_BYTES = 2 * SMEM_WORDS_HALF * (int)sizeof(float);   // 81920

// big GEMM: 128x256, 8 warps of 64x64, 3 stages
constexpr int BBM = 128, BBN = 256, BBK = 16;
constexpr int BSTAGES = 3;
constexpr int BIG_A_WORDS = BSTAGES * BBM * PADK;    // 7680
constexpr int BIG_B_WORDS = BSTAGES * BBN * PADK;    // 15360
constexpr int BIG_SMEM_BYTES = (BIG_A_WORDS + BIG_B_WORDS) * (int)sizeof(float); // 92160

constexpr int PVSPLIT = 4;
constexpr int PVK = NS / PVSPLIT;    // 256
}

// ---------------------------------------------------------------------------
// Static device scratch (no allocations allowed)
// ---------------------------------------------------------------------------
__device__ float d_xn[NT * NHID];
__device__ float d_qt[NT * NHID];
__device__ float d_kt[NT * NHID];
__device__ float d_vt[NT * NHID];
__device__ float d_qr[NT * NHID];     // (B,NH,S,HD) rope'd + scaled, tf32-rounded
__device__ float d_kr[NT * NHID];     // (B,NH,S,HD) tf32-rounded
__device__ float d_vrT[NT * NHID];    // (B,NH,HD,S) tf32-rounded
__device__ float d_scores[(long)NB * NHEAD * NS * NS];   // 64 MB
__device__ float d_ctx[NT * NHID];
__device__ float d_pvp[(long)PVSPLIT * NT * NHID];       // partial planes (reused)
__device__ float d_x1[NT * NHID];
__device__ float d_xg[NSLOT * NHID];
__device__ float d_gbuf[NSLOT * NMI];
__device__ float d_ubuf[NSLOT * NMI];
__device__ float d_ybuf[NSLOT * NHID];
__device__ float d_gs[NT * NSI];
__device__ float d_us[NT * NSI];
__device__ int   d_cnt[NEXP];
__device__ int   d_off[NEXP];
__device__ int   d_e0[NT], d_e1[NT], d_r0[NT], d_r1[NT], d_s0[NT], d_s1[NT];
__device__ float d_w0[NT], d_w1[NT];

// ---------------------------------------------------------------------------
// helpers
// ---------------------------------------------------------------------------
__device__ __forceinline__ unsigned smem_u32(const void* p) {
    return (unsigned)__cvta_generic_to_shared(p);
}

__device__ __forceinline__ void cp16(unsigned dst, const void* src, bool pred) {
    int sz = pred ? 16 : 0;
    asm volatile("cp.async.cg.shared.global [%0], [%1], 16, %2;\n"
                 :: "r"(dst), "l"(src), "r"(sz));
}

// RNA-round an fp32 value to tf32 precision (result stays an fp32 value)
__device__ __forceinline__ float rna(float x) {
    unsigned u;
    asm("cvt.rna.tf32.f32 %0, %1;" : "=r"(u) : "f"(x));
    return __uint_as_float(u);
}

__device__ __forceinline__ void mma_tf32(float c[4],
    unsigned a0, unsigned a1, unsigned a2, unsigned a3,
    unsigned b0, unsigned b1)
{
    asm volatile(
        "mma.sync.aligned.m16n8k8.row.col.f32.tf32.tf32.f32 "
        "{%0,%1,%2,%3}, {%4,%5,%6,%7}, {%8,%9}, {%0,%1,%2,%3};\n"
        : "+f"(c[0]), "+f"(c[1]), "+f"(c[2]), "+f"(c[3])
        : "r"(a0), "r"(a1), "r"(a2), "r"(a3), "r"(b0), "r"(b1));
}

// ---------------------------------------------------------------------------
// BIG GEMM: C[M,N] = A[M,K] * B^T, B stored (N,K) row-major.
// 128x256 block, 256 thr = 8 warps, each warp 64x64 (4x8 m16n8k8).
// 3-stage cp.async, one __syncthreads per k-iter. M ragged OK.
// Operands fed as raw fp32 (HW truncates to tf32; producers RNA-round).
// ---------------------------------------------------------------------------
__device__ __forceinline__ void big_body(
    const float* __restrict__ A, const float* __restrict__ Bm,
    float* __restrict__ C, int M, int K, int lda, int ldb, int ldc)
{
    extern __shared__ float sm[];
    float* Asm = sm;                     // [BSTAGES][BBM][PADK]
    float* Bsm = sm + BIG_A_WORDS;       // [BSTAGES][BBN][PADK]

    const int tid  = threadIdx.x;
    const int wid  = tid >> 5;
    const int lane = tid & 31;
    const int g    = lane >> 2;          // 0..7
    const int tg   = lane & 3;           // 0..3
    const int wm   = (wid & 1) * 64;
    const int wn   = (wid >> 1) * 64;
    const int row0 = blockIdx.y * BBM;
    const int col0 = blockIdx.x * BBN;
    if (row0 >= M) return;

    float c[4][8][4];
#pragma unroll
    for (int mi = 0; mi < 4; ++mi)
#pragma unroll
        for (int ni = 0; ni < 8; ++ni)
#pragma unroll
            for (int r = 0; r < 4; ++r) c[mi][ni][r] = 0.f;

    const int ar = tid >> 2;             // 0..63
    const int aq = (tid & 3) * 4;        // 0,4,8,12
    const int niter = K / BBK;

    // ---- prologue: stages 0,1 ----
#pragma unroll
    for (int st = 0; st < BSTAGES - 1; ++st) {
        if (st < niter) {
            const int k0 = st * BBK;
            float* As = Asm + st * BBM * PADK;
            float* Bs = Bsm + st * BBN * PADK;
#pragma unroll
            for (int h = 0; h < 2; ++h) {
                int r = ar + h * 64;
                cp16(smem_u32(As + r * PADK + aq),
                     A + (long)(row0 + r) * lda + k0 + aq, (row0 + r) < M);
            }
#pragma unroll
            for (int h = 0; h < 4; ++h) {
                int r = ar + h * 64;
                cp16(smem_u32(Bs + r * PADK + aq),
                     Bm + (long)(col0 + r) * ldb + k0 + aq, true);
            }
        }
        asm volatile("cp.async.commit_group;\n");
    }

    int s = 0;
    for (int it = 0; it < niter; ++it) {
        asm volatile("cp.async.wait_group 1;\n");
        __syncthreads();

        const int pf = it + BSTAGES - 1;
        if (pf < niter) {
            int sl = s + BSTAGES - 1; if (sl >= BSTAGES) sl -= BSTAGES;
            const int k0 = pf * BBK;
            float* As = Asm + sl * BBM * PADK;
            float* Bs = Bsm + sl * BBN * PADK;
#pragma unroll
            for (int h = 0; h < 2; ++h) {
                int r = ar + h * 64;
                cp16(smem_u32(As + r * PADK + aq),
                     A + (long)(row0 + r) * lda + k0 + aq, (row0 + r) < M);
            }
#pragma unroll
            for (int h = 0; h < 4; ++h) {
                int r = ar + h * 64;
                cp16(smem_u32(Bs + r * PADK + aq),
                     Bm + (long)(col0 + r) * ldb + k0 + aq, true);
            }
        }
        asm volatile("cp.async.commit_group;\n");

        const float* As = Asm + s * BBM * PADK;
        const float* Bs = Bsm + s * BBN * PADK;
#pragma unroll
        for (int kk = 0; kk < 2; ++kk) {
            const int kb = kk * 8;
            unsigned af[4][4], bf[8][2];
#pragma unroll
            for (int mi = 0; mi < 4; ++mi) {
                const float* p = As + (wm + mi * 16 + g) * PADK + kb + tg;
                af[mi][0] = __float_as_uint(p[0]);
                af[mi][1] = __float_as_uint(p[8 * PADK]);
                af[mi][2] = __float_as_uint(p[4]);
                af[mi][3] = __float_as_uint(p[8 * PADK + 4]);
            }
#pragma unroll
            for (int ni = 0; ni < 8; ++ni) {
                const float* p = Bs + (wn + ni * 8 + g) * PADK + kb + tg;
                bf[ni][0] = __float_as_uint(p[0]);
                bf[ni][1] = __float_as_uint(p[4]);
            }
#pragma unroll
            for (int mi = 0; mi < 4; ++mi)
#pragma unroll
                for (int ni = 0; ni < 8; ++ni)
                    mma_tf32(c[mi][ni], af[mi][0], af[mi][1], af[mi][2], af[mi][3],
                             bf[ni][0], bf[ni][1]);
        }
        if (++s >= BSTAGES) s = 0;
    }

    // ---- epilogue ----
#pragma unroll
    for (int mi = 0; mi < 4; ++mi) {
#pragma unroll
        for (int half = 0; half < 2; ++half) {
            int r = row0 + wm + mi * 16 + g + half * 8;
            if (r < M) {
#pragma unroll
                for (int ni = 0; ni < 8; ++ni) {
                    long off = (long)r * ldc + col0 + wn + ni * 8 + tg * 2;
                    float2 v;
                    v.x = c[mi][ni][half * 2 + 0];
                    v.y = c[mi][ni][half * 2 + 1];
                    *(float2*)(C + off) = v;
                }
            }
        }
    }
}

// ---- generic batched big GEMM (scores causal, split-K via sA/sB/sC_lo)
template <bool CAUSAL>
__global__ __launch_bounds__(256, 1)
void big_bat(
    const float* __restrict__ A, const float* __restrict__ Bm,
    float* __restrict__ C,
    int M, int K, int lda, int ldb, int ldc,
    long sA, long sB, long sC_hi, long sC_lo)
{
    int z = blockIdx.z;
    if (CAUSAL) {
        if (2 * (int)blockIdx.x > (int)blockIdx.y) return;  // above diagonal
    }
    big_body(A + (long)z * sA, Bm + (long)z * sB,
             C + (long)(z >> 3) * sC_hi + (long)(z & 7) * sC_lo,
             M, K, lda, ldb, ldc);
}

// ---- fused Q/K/V projection
__global__ __launch_bounds__(256, 1)
void big_qkv(const float* __restrict__ xn,
             const float* __restrict__ qw, const float* __restrict__ kw,
             const float* __restrict__ vw,
             float* __restrict__ qt, float* __restrict__ kt, float* __restrict__ vt)
{
    int z = blockIdx.z;
    const float* B = (z == 0) ? qw : (z == 1) ? kw : vw;
    float* C       = (z == 0) ? qt : (z == 1) ? kt : vt;
    big_body(xn, B, C, NT, NHID, NHID, NHID, NHID);
}

// ---- fused shared-MLP gate+up
__global__ __launch_bounds__(256, 1)
void big_shup(const float* __restrict__ xn,
              const float* __restrict__ sg, const float* __restrict__ su,
              float* __restrict__ gs, float* __restrict__ us)
{
    int z = blockIdx.z;
    big_body(xn, z ? su : sg, z ? us : gs, NT, NHID, NHID, NHID, NSI);
}

// ---- fused MoE gate+up grouped: z = 2*e + which
__global__ __launch_bounds__(256, 1)
void big_moeup(const float* __restrict__ xg,
               const float* __restrict__ eg, const float* __restrict__ eu,
               float* __restrict__ gb, float* __restrict__ ub)
{
    int z = blockIdx.z;
    int e = z >> 1;
    int M = d_cnt[e];
    int off = d_off[e];
    const float* B = (z & 1) ? eu : eg;
    float* C       = (z & 1) ? ub : gb;
    big_body(xg + (long)off * NHID, B + (long)e * NMI * NHID,
             C + (long)off * NMI, M, NHID, NHID, NHID, NMI);
}

// ---- MoE down grouped
__global__ __launch_bounds__(256, 1)
void big_moedn(const float* __restrict__ gb, const float* __restrict__ ed,
               float* __restrict__ yb)
{
    int e = blockIdx.z;
    int M = d_cnt[e];
    int off = d_off[e];
    big_body(gb + (long)off * NMI, ed + (long)e * NHID * NMI,
             yb + (long)off * NHID, M, NMI, NMI, NMI, NHID);
}

// ---------------------------------------------------------------------------
// Small GEMM (PV only): 128x128, 8 warps of 64x32, 4-stage pipeline
// ---------------------------------------------------------------------------
__device__ __forceinline__ void mmgemm_body(
    const float* __restrict__ A, const float* __restrict__ Bm,
    float* __restrict__ C, int M, int K, int lda, int ldb, int ldc)
{
    extern __shared__ float sm[];
    float (*As)[BM][PADK] = reinterpret_cast<float (*)[BM][PADK]>(sm);
    float (*Bs)[BM][PADK] =
        reinterpret_cast<float (*)[BM][PADK]>(sm + SMEM_WORDS_HALF);

    const int tid  = threadIdx.x;
    const int wid  = tid >> 5;
    const int lane = tid & 31;
    const int g    = lane >> 2;
    const int tg   = lane & 3;
    const int wm   = (wid & 1) * 64;
    const int wn   = (wid >> 1) * 32;
    const int row0 = blockIdx.y * BM;
    const int col0 = blockIdx.x * BN;
    if (row0 >= M) return;

    float c[4][4][4];
#pragma unroll
    for (int mi = 0; mi < 4; ++mi)
#pragma unroll
        for (int ni = 0; ni < 4; ++ni)
#pragma unroll
            for (int r = 0; r < 4; ++r) c[mi][ni][r] = 0.f;

    const int lr = tid >> 2;
    const int lq = (tid & 3) * 4;
    const int niter = K / BK;

#pragma unroll
    for (int st = 0; st < STAGES - 1; ++st) {
        if (st < niter) {
            const int k0 = st * BK;
#pragma unroll
            for (int h = 0; h < 2; ++h) {
                int r = lr + h * 64;
                cp16(smem_u32(&As[st][r][lq]),
                     A + (long)(row0 + r) * lda + k0 + lq, (row0 + r) < M);
            }
#pragma unroll
            for (int h = 0; h < 2; ++h) {
                int r = lr + h * 64;
                cp16(smem_u32(&Bs[st][r][lq]),
                     Bm + (long)(col0 + r) * ldb + k0 + lq, true);
            }
        }
        asm volatile("cp.async.commit_group;\n");
    }

    int s = 0;
    for (int it = 0; it < niter; ++it) {
        asm volatile("cp.async.wait_group 2;\n");
        __syncthreads();

        const int pf = it + STAGES - 1;
        if (pf < niter) {
            int sl = s + STAGES - 1; if (sl >= STAGES) sl -= STAGES;
            const int k0 = pf * BK;
#pragma unroll
            for (int h = 0; h < 2; ++h) {
                int r = lr + h * 64;
                cp16(smem_u32(&As[sl][r][lq]),
                     A + (long)(row0 + r) * lda + k0 + lq, (row0 + r) < M);
            }
#pragma unroll
            for (int h = 0; h < 2; ++h) {
                int r = lr + h * 64;
                cp16(smem_u32(&Bs[sl][r][lq]),
                     Bm + (long)(col0 + r) * ldb + k0 + lq, true);
            }
        }
        asm volatile("cp.async.commit_group;\n");

#pragma unroll
        for (int kk = 0; kk < 2; ++kk) {
            const int kb = kk * 8;
            unsigned af[4][4], bf[4][2];
#pragma unroll
            for (int mi = 0; mi < 4; ++mi) {
                int mrow = wm + mi * 16;
                af[mi][0] = __float_as_uint(As[s][mrow + g    ][kb + tg    ]);
                af[mi][1] = __float_as_uint(As[s][mrow + g + 8][kb + tg    ]);
                af[mi][2] = __float_as_uint(As[s][mrow + g    ][kb + tg + 4]);
                af[mi][3] = __float_as_uint(As[s][mrow + g + 8][kb + tg + 4]);
            }
#pragma unroll
            for (int ni = 0; ni < 4; ++ni) {
                int nrow = wn + ni * 8;
                bf[ni][0] = __float_as_uint(Bs[s][nrow + g][kb + tg    ]);
                bf[ni][1] = __float_as_uint(Bs[s][nrow + g][kb + tg + 4]);
            }
#pragma unroll
            for (int mi = 0; mi < 4; ++mi)
#pragma unroll
                for (int ni = 0; ni < 4; ++ni)
                    mma_tf32(c[mi][ni], af[mi][0], af[mi][1], af[mi][2], af[mi][3],
                             bf[ni][0], bf[ni][1]);
        }
        if (++s >= STAGES) s = 0;
    }

#pragma unroll
    for (int mi = 0; mi < 4; ++mi) {
#pragma unroll
        for (int half = 0; half < 2; ++half) {
            int r = row0 + wm + mi * 16 + g + half * 8;
            if (r < M) {
#pragma unroll
                for (int ni = 0; ni < 4; ++ni) {
                    long off = (long)r * ldc + col0 + wn + ni * 8 + tg * 2;
                    float2 v;
                    v.x = c[mi][ni][half * 2 + 0];
                    v.y = c[mi][ni][half * 2 + 1];
                    *(float2*)(C + off) = v;
                }
            }
        }
    }
}

// ---- PV with split-K: z = head*PVSPLIT + chunk; writes partial planes
__global__ __launch_bounds__(256, 2)
void pv_k(const float* __restrict__ sc, const float* __restrict__ vrT,
          float* __restrict__ pvp)
{
    int z = blockIdx.z;
    int head = z >> 2, chunk = z & 3;
    mmgemm_body(sc  + (long)head * NS * NS    + chunk * PVK,
                vrT + (long)head * DHEAD * NS + chunk * PVK,
                pvp + (long)chunk * NT * NHID
                    + (long)(head >> 3) * NS * NHID + (head & 7) * DHEAD,
                NS, PVK, NS, NS, NHID);
}

// ---- reduce PV partials into ctx (tf32-rounded; feeds O-proj)
__global__ void pvred_k(const float* __restrict__ pvp, float* __restrict__ ctx)
{
    long i = (long)blockIdx.x * 256 + threadIdx.x;
    const long P = (long)NT * NHID;
    float v = pvp[i] + pvp[i + P] + pvp[i + 2 * P] + pvp[i + 3 * P];
    ctx[i] = rna(v);
}

// ---- reduce 2 split-K planes + residual (O-proj epilogue)
__global__ void red2_k(const float* __restrict__ p, const float* __restrict__ resid,
                       float* __restrict__ out)
{
    long i = (long)blockIdx.x * 256 + threadIdx.x;
    const long P = (long)NT * NHID;
    out[i] = resid[i] + p[i] + p[i + P];
}

// ---------------------------------------------------------------------------
// Elementwise / reduction kernels (GEMM-feeding outputs are tf32 RNA-rounded)
// ---------------------------------------------------------------------------
__global__ void rmsnorm_k(const float* __restrict__ x,
                          const float* __restrict__ w,
                          float* __restrict__ o)
{
    int t = blockIdx.x;
    const float* xr = x + (long)t * NHID;
    __shared__ float red[256];
    float s = 0.f;
    for (int i = threadIdx.x; i < NHID; i += 256) { float v = xr[i]; s += v * v; }
    red[threadIdx.x] = s;
    __syncthreads();
    for (int st = 128; st > 0; st >>= 1) {
        if (threadIdx.x < st) red[threadIdx.x] += red[threadIdx.x + st];
        __syncthreads();
    }
    float scale = rsqrtf(red[0] / (float)NHID + 1e-6f);
    for (int i = threadIdx.x; i < NHID; i += 256)
        o[(long)t * NHID + i] = rna(xr[i] * scale * w[i]);
}

__global__ void rope_k(const float* __restrict__ qt, const float* __restrict__ kt,
                       const float* __restrict__ vt,
                       const float* __restrict__ cosp, const float* __restrict__ sinp,
                       float* __restrict__ qr, float* __restrict__ kr,
                       float* __restrict__ vrT)
{
    int t = blockIdx.x;                // token
    int n = blockIdx.y;                // head
    int d = threadIdx.x;               // 0..63
    int b = t / NS, s = t % NS;
    long src = (long)t * NHID + n * DHEAD;
    long dst = ((long)(b * NHEAD + n) * NS + s) * DHEAD;
    long bhv = (long)(b * NHEAD + n) * DHEAD * NS;
    float c  = cosp[s * DHEAD + d];
    float sn = sinp[s * DHEAD + d];
    const float inv = 0.08838834764831845f;  // 1/sqrt(128)

    float q0 = qt[src + d], q1 = qt[src + d + 64];
    qr[dst + d]      = rna((q0 * c - q1 * sn) * inv);
    qr[dst + d + 64] = rna((q1 * c + q0 * sn) * inv);

    float k0 = kt[src + d], k1 = kt[src + d + 64];
    kr[dst + d]      = rna(k0 * c - k1 * sn);
    kr[dst + d + 64] = rna(k1 * c + k0 * sn);

    vrT[bhv + (long)d * NS + s]        = rna(vt[src + d]);
    vrT[bhv + (long)(d + 64) * NS + s] = rna(vt[src + d + 64]);
}

__global__ void softmax_causal_k(float* __restrict__ sc)
{
    int q  = blockIdx.x;
    int bh = blockIdx.y;
    float* row = sc + (long)bh * NS * NS + (long)q * NS;
    int len = q + 1;
    __shared__ float red[256];
    int tid = threadIdx.x;

    float m = -1e30f;
    for (int i = tid; i < len; i += 256) m = fmaxf(m, row[i]);
    red[tid] = m;
    __syncthreads();
    for (int st = 128; st > 0; st >>= 1) {
        if (tid < st) red[tid] = fmaxf(red[tid], red[tid + st]);
        __syncthreads();
    }
    m = red[0];
    __syncthreads();

    float s = 0.f;
    for (int i = tid; i < len; i += 256) {
        float e = expf(row[i] - m);
        row[i] = e;
        s += e;
    }
    red[tid] = s;
    __syncthreads();
    for (int st = 128; st > 0; st >>= 1) {
        if (tid < st) red[tid] += red[tid + st];
        __syncthreads();
    }
    float invs = 1.f / red[0];
    for (int i = tid; i < NS; i += 256) {
        if (i < len) row[i] = rna(row[i] * invs);
        else         row[i] = 0.f;
    }
}

__global__ void zero_cnt_k() { if (threadIdx.x < NEXP) d_cnt[threadIdx.x] = 0; }

__global__ void gate_k(const float* __restrict__ xn, const float* __restrict__ gw)
{
    int t = blockIdx.x;
    int tid = threadIdx.x, w = tid >> 5, lane = tid & 31;
    const float* xr = xn + (long)t * NHID;
    const float* gr = gw + (long)w * NHID;
    float s = 0.f;
    for (int i = lane; i < NHID; i += 32) s += xr[i] * gr[i];
    for (int o = 16; o; o >>= 1) s += __shfl_xor_sync(0xffffffffu, s, o);
    __shared__ float lg[NEXP];
    if (lane == 0) lg[w] = s;
    __syncthreads();
    if (tid == 0) {
        float mx = lg[0];
        for (int e = 1; e < NEXP; ++e) mx = fmaxf(mx, lg[e]);
        float p[NEXP];
        for (int e = 0; e < NEXP; ++e) p[e] = expf(lg[e] - mx);
        int e0 = 0; float b0 = p[0];
        for (int e = 1; e < NEXP; ++e) if (p[e] > b0) { b0 = p[e]; e0 = e; }
        int e1 = -1; float b1 = -1.f;
        for (int e = 0; e < NEXP; ++e)
            if (e != e0 && p[e] > b1) { b1 = p[e]; e1 = e; }
        float denom = b0 + b1;
        d_e0[t] = e0; d_e1[t] = e1;
        d_w0[t] = b0 / denom; d_w1[t] = b1 / denom;
        d_r0[t] = atomicAdd(&d_cnt[e0], 1);
        d_r1[t] = atomicAdd(&d_cnt[e1], 1);
    }
}

__global__ void scan_k()
{
    if (threadIdx.x == 0) {
        int a = 0;
        for (int e = 0; e < NEXP; ++e) { d_off[e] = a; a += d_cnt[e]; }
    }
}

__global__ void gather_k(const float* __restrict__ xn)
{
    int t = blockIdx.x;
    __shared__ int ss[2];
    if (threadIdx.x == 0) {
        int s0 = d_off[d_e0[t]] + d_r0[t];
        int s1 = d_off[d_e1[t]] + d_r1[t];
        d_s0[t] = s0; d_s1[t] = s1;
        ss[0] = s0; ss[1] = s1;
    }
    __syncthreads();
    const float4* src = (const float4*)(xn + (long)t * NHID);
    float4* dst0 = (float4*)(d_xg + (long)ss[0] * NHID);
    float4* dst1 = (float4*)(d_xg + (long)ss[1] * NHID);
    for (int i = threadIdx.x; i < NHID / 4; i += 256) {
        float4 v = src[i];
        dst0[i] = v;
        dst1[i] = v;
    }
}

__global__ void silumul_k(float* __restrict__ g, const float* __restrict__ u, long n)
{
    long i = (long)blockIdx.x * 256 + threadIdx.x;
    if (i < n) {
        float gv = g[i];
        float s = 1.f / (1.f + expf(-gv));
        g[i] = rna(gv * s * u[i]);
    }
}

// out = x1 + (shdown plane0 + plane1) + routed
__global__ void combine_k(const float* __restrict__ x1,
                          const float* __restrict__ shp,
                          float* __restrict__ out)
{
    int t = blockIdx.x;
    float w0 = d_w0[t], w1 = d_w1[t];
    long o0 = (long)d_s0[t] * NHID;
    long o1 = (long)d_s1[t] * NHID;
    const long P = (long)NT * NHID;
    for (int i = threadIdx.x; i < NHID; i += 256) {
        long idx = (long)t * NHID + i;
        out[idx] = x1[idx] + shp[idx] + shp[idx + P]
                 + w0 * d_ybuf[o0 + i] + w1 * d_ybuf[o1 + i];
    }
}

// ---------------------------------------------------------------------------
// Launch
// ---------------------------------------------------------------------------
extern "C" void kernel_launch(void* const* d_in, const int* in_sizes, int n_in,
                              void* d_out, int out_size)
{
    (void)in_sizes; (void)n_in; (void)out_size;

    const float* hs   = (const float*)d_in[0];
    const float* ln1  = (const float*)d_in[1];
    const float* ln2  = (const float*)d_in[2];
    const float* q_w  = (const float*)d_in[3];
    const float* k_w  = (const float*)d_in[4];
    const float* v_w  = (const float*)d_in[5];
    const float* o_w  = (const float*)d_in[6];
    const float* cosp = (const float*)d_in[7];
    const float* sinp = (const float*)d_in[8];
    const float* gate = (const float*)d_in[9];
    const float* eg   = (const float*)d_in[10];
    const float* eu   = (const float*)d_in[11];
    const float* ed   = (const float*)d_in[12];
    const float* sg   = (const float*)d_in[13];
    const float* su   = (const float*)d_in[14];
    const float* sd   = (const float*)d_in[15];
    float* out = (float*)d_out;

    float *xn, *qt, *kt, *vt, *qr, *kr, *vrT, *sc, *ctx, *pvp, *x1;
    float *xg, *gb, *ub, *yb, *gs, *us;
    cudaGetSymbolAddress((void**)&xn,  d_xn);
    cudaGetSymbolAddress((void**)&qt,  d_qt);
    cudaGetSymbolAddress((void**)&kt,  d_kt);
    cudaGetSymbolAddress((void**)&vt,  d_vt);
    cudaGetSymbolAddress((void**)&qr,  d_qr);
    cudaGetSymbolAddress((void**)&kr,  d_kr);
    cudaGetSymbolAddress((void**)&vrT, d_vrT);
    cudaGetSymbolAddress((void**)&sc,  d_scores);
    cudaGetSymbolAddress((void**)&ctx, d_ctx);
    cudaGetSymbolAddress((void**)&pvp, d_pvp);
    cudaGetSymbolAddress((void**)&x1,  d_x1);
    cudaGetSymbolAddress((void**)&xg,  d_xg);
    cudaGetSymbolAddress((void**)&gb,  d_gbuf);
    cudaGetSymbolAddress((void**)&ub,  d_ubuf);
    cudaGetSymbolAddress((void**)&yb,  d_ybuf);
    cudaGetSymbolAddress((void**)&gs,  d_gs);
    cudaGetSymbolAddress((void**)&us,  d_us);

    cudaFuncSetAttribute(big_bat<false>,
        cudaFuncAttributeMaxDynamicSharedMemorySize, BIG_SMEM_BYTES);
    cudaFuncSetAttribute(big_bat<true>,
        cudaFuncAttributeMaxDynamicSharedMemorySize, BIG_SMEM_BYTES);
    cudaFuncSetAttribute(big_qkv,
        cudaFuncAttributeMaxDynamicSharedMemorySize, BIG_SMEM_BYTES);
    cudaFuncSetAttribute(big_shup,
        cudaFuncAttributeMaxDynamicSharedMemorySize, BIG_SMEM_BYTES);
    cudaFuncSetAttribute(big_moeup,
        cudaFuncAttributeMaxDynamicSharedMemorySize, BIG_SMEM_BYTES);
    cudaFuncSetAttribute(big_moedn,
        cudaFuncAttributeMaxDynamicSharedMemorySize, BIG_SMEM_BYTES);
    cudaFuncSetAttribute(pv_k,
        cudaFuncAttributeMaxDynamicSharedMemorySize, SMEM_BYTES);

    const long PLANE = (long)NT * NHID;

    const dim3 gQKV(NHID / BBN, NT / BBM, 3);              // (4,16,3)
    const dim3 gScore(NS / BBN, NS / BBM, NB * NHEAD);     // (4,8,16)
    const dim3 gPV(1, NS / BM, NB * NHEAD * PVSPLIT);      // (1,8,64)
    const dim3 gOproj(NHID / BBN, NT / BBM, 2);            // (4,16,2) split-K
    const dim3 gShUp(NSI / BBN, NT / BBM, 2);              // (8,16,2)
    const dim3 gMoeUp(NMI / BBN, NSLOT / BBM, 2 * NEXP);   // (4,32,16)
    const dim3 gMoeDn(NHID / BBN, NSLOT / BBM, NEXP);      // (4,32,8)
    const dim3 gShDn(NHID / BBN, NT / BBM, 2);             // (4,16,2) split-K

    // ---- attention ----
    rmsnorm_k<<<NT, 256>>>(hs, ln1, xn);
    big_qkv<<<gQKV, 256, BIG_SMEM_BYTES>>>(xn, q_w, k_w, v_w, qt, kt, vt);
    rope_k<<<dim3(NT, NHEAD), 64>>>(qt, kt, vt, cosp, sinp, qr, kr, vrT);

    big_bat<true><<<gScore, 256, BIG_SMEM_BYTES>>>(qr, kr, sc,
        NS, DHEAD, DHEAD, DHEAD, NS,
        (long)NS * DHEAD, (long)NS * DHEAD,
        8L * NS * NS, (long)NS * NS);
    softmax_causal_k<<<dim3(NS, NB * NHEAD), 256>>>(sc);
    pv_k<<<gPV, 256, SMEM_BYTES>>>(sc, vrT, pvp);
    pvred_k<<<(unsigned)(PLANE / 256), 256>>>(pvp, ctx);

    // O-proj split-K=2 into pvp planes 0,1 then reduce with residual
    big_bat<false><<<gOproj, 256, BIG_SMEM_BYTES>>>(ctx, o_w, pvp,
        NT, NHID / 2, NHID, NHID, NHID,
        (long)(NHID / 2), (long)(NHID / 2), 0, PLANE);
    red2_k<<<(unsigned)(PLANE / 256), 256>>>(pvp, hs, x1);

    // ---- MoE ----
    rmsnorm_k<<<NT, 256>>>(x1, ln2, xn);
    zero_cnt_k<<<1, 32>>>();
    gate_k<<<NT, 256>>>(xn, gate);
    scan_k<<<1, 1>>>();
    gather_k<<<NT, 256>>>(xn);

    big_moeup<<<gMoeUp, 256, BIG_SMEM_BYTES>>>(xg, eg, eu, gb, ub);
    silumul_k<<<(unsigned)(((long)NSLOT * NMI + 255) / 256), 256>>>(
        gb, ub, (long)NSLOT * NMI);
    big_moedn<<<gMoeDn, 256, BIG_SMEM_BYTES>>>(gb, ed, yb);

    // ---- shared MLP ----
    big_shup<<<gShUp, 256, BIG_SMEM_BYTES>>>(xn, sg, su, gs, us);
    silumul_k<<<(unsigned)(((long)NT * NSI + 255) / 256), 256>>>(
        gs, us, (long)NT * NSI);
    // shared-down split-K=2 into pvp planes 0,1 (free after red2_k)
    big_bat<false><<<gShDn, 256, BIG_SMEM_BYTES>>>(gs, sd, pvp,
        NT, NSI / 2, NSI, NSI, NHID,
        (long)(NSI / 2), (long)(NSI / 2), 0, PLANE);

    // ---- combine ----
    combine_k<<<NT, 256>>>(x1, pvp, out);
}

// round 7
// speedup vs baseline: 1.3770x; 1.3770x over previous
#include <cuda_runtime.h>
#include <cuda_fp16.h>
#include <math.h>

// ---------------------------------------------------------------------------
// Problem constants
// ---------------------------------------------------------------------------
namespace {
constexpr int NB = 2, NS = 1024, NHID = 1024, NHEAD = 8, DHEAD = 128;
constexpr int NEXP = 8, NMI = 1024, NSI = 2048;
constexpr int NT = NB * NS;          // 2048 tokens
constexpr int NSLOT = 2 * NT;        // 4096 expert slots (top-2)

// fp16 GEMM tile: 128x128x32(halves), 8 warps of 64x32, 4-stage cp.async
constexpr int BM = 128, BN = 128, BKH = 32;     // BKH halves per k-iter
constexpr int PAD32 = 20;                        // row stride in b32 (80B, 16B-aligned)
constexpr int STAGES = 4;
constexpr int STAGE_WORDS = BM * PAD32;          // 2560 b32 per tile-stage
constexpr int SMEM_BYTES = 2 * STAGES * STAGE_WORDS * 4;   // 81920

constexpr int PVSPLIT = 4;
constexpr int PVK = NS / PVSPLIT;    // 256
}

// ---------------------------------------------------------------------------
// Static device scratch (no allocations allowed)
// ---------------------------------------------------------------------------
// fp32 buffers
__device__ float d_xn32[NT * NHID];                      // for gating (fp32 path)
__device__ float d_qt[NT * NHID];
__device__ float d_kt[NT * NHID];
__device__ float d_vt[NT * NHID];
__device__ float d_scores[(long)NB * NHEAD * NS * NS];   // 64 MB (QK^T out)
__device__ float d_pvp[(long)PVSPLIT * NT * NHID];       // PV split-K partials
__device__ float d_x1[NT * NHID];
__device__ float d_gbuf[NSLOT * NMI];
__device__ float d_ubuf[NSLOT * NMI];
__device__ float d_ybuf[NSLOT * NHID];
__device__ float d_gs[NT * NSI];
__device__ float d_us[NT * NSI];
__device__ float d_sh[NT * NHID];
// fp16 buffers (GEMM operands)
__device__ __half h_qw[NHID * NHID];
__device__ __half h_kw[NHID * NHID];
__device__ __half h_vw[NHID * NHID];
__device__ __half h_ow[NHID * NHID];
__device__ __half h_eg[NEXP * NMI * NHID];
__device__ __half h_eu[NEXP * NMI * NHID];
__device__ __half h_ed[NEXP * NHID * NMI];
__device__ __half h_sg[NSI * NHID];
__device__ __half h_su[NSI * NHID];
__device__ __half h_sd[NHID * NSI];
__device__ __half h_xn[NT * NHID];
__device__ __half h_qr[NT * NHID];    // (B,NH,S,HD)
__device__ __half h_kr[NT * NHID];    // (B,NH,S,HD)
__device__ __half h_vrT[NT * NHID];   // (B,NH,HD,S)
__device__ __half h_probs[(long)NB * NHEAD * NS * NS];   // 32 MB
__device__ __half h_ctx[NT * NHID];
__device__ __half h_xg[NSLOT * NHID];
__device__ __half h_gb[NSLOT * NMI];
__device__ __half h_gs[NT * NSI];
// routing state
__device__ int   d_cnt[NEXP];
__device__ int   d_off[NEXP];
__device__ int   d_e0[NT], d_e1[NT], d_r0[NT], d_r1[NT], d_s0[NT], d_s1[NT];
__device__ float d_w0[NT], d_w1[NT];

// ---------------------------------------------------------------------------
// helpers
// ---------------------------------------------------------------------------
__device__ __forceinline__ unsigned smem_u32(const void* p) {
    return (unsigned)__cvta_generic_to_shared(p);
}

__device__ __forceinline__ void cp16(unsigned dst, const void* src, bool pred) {
    int sz = pred ? 16 : 0;
    asm volatile("cp.async.cg.shared.global [%0], [%1], 16, %2;\n"
                 :: "r"(dst), "l"(src), "r"(sz));
}

__device__ __forceinline__ void mma_f16(float c[4],
    unsigned a0, unsigned a1, unsigned a2, unsigned a3,
    unsigned b0, unsigned b1)
{
    asm volatile(
        "mma.sync.aligned.m16n8k16.row.col.f32.f16.f16.f32 "
        "{%0,%1,%2,%3}, {%4,%5,%6,%7}, {%8,%9}, {%0,%1,%2,%3};\n"
        : "+f"(c[0]), "+f"(c[1]), "+f"(c[2]), "+f"(c[3])
        : "r"(a0), "r"(a1), "r"(a2), "r"(a3), "r"(b0), "r"(b1));
}

// ---------------------------------------------------------------------------
// FP16 tensor-core GEMM:  C[M,N] = A[M,K] * B^T  (B stored (N,K) row-major,
// all element offsets/lds in HALVES).  128x128 block, 8 warps of 64x32
// (4x4 m16n8k16), 4-stage cp.async, one __syncthreads per k-iter.
// M may be ragged (zfill + store guards). N mult of 128, K mult of 32.
// ---------------------------------------------------------------------------
__device__ __forceinline__ void hgemm_body(
    const __half* __restrict__ A, const __half* __restrict__ Bm,
    float* __restrict__ C, const float* __restrict__ resid,
    int M, int K, int lda, int ldb, int ldc)
{
    extern __shared__ unsigned smu[];
    unsigned* Asm = smu;                         // [STAGES][BM][PAD32]
    unsigned* Bsm = smu + STAGES * STAGE_WORDS;

    const int tid  = threadIdx.x;
    const int wid  = tid >> 5;
    const int lane = tid & 31;
    const int g    = lane >> 2;          // 0..7
    const int tg   = lane & 3;           // 0..3
    const int wm   = (wid & 1) * 64;
    const int wn   = (wid >> 1) * 32;
    const int row0 = blockIdx.y * BM;
    const int col0 = blockIdx.x * BN;
    if (row0 >= M) return;

    float c[4][4][4];
#pragma unroll
    for (int mi = 0; mi < 4; ++mi)
#pragma unroll
        for (int ni = 0; ni < 4; ++ni)
#pragma unroll
            for (int r = 0; r < 4; ++r) c[mi][ni][r] = 0.f;

    const int lr = tid >> 1;             // 0..127  (row within tile)
    const int lqh = (tid & 1) * 16;      // half-offset 0/16
    const int lqw = (tid & 1) * 8;       // b32-offset 0/8
    const int niter = K / BKH;

    // ---- prologue: stages 0..2 ----
#pragma unroll
    for (int st = 0; st < STAGES - 1; ++st) {
        if (st < niter) {
            const int k0 = st * BKH;
            const __half* ga = A + (long)(row0 + lr) * lda + k0 + lqh;
            unsigned da = smem_u32(Asm + st * STAGE_WORDS + lr * PAD32 + lqw);
            bool pa = (row0 + lr) < M;
            cp16(da,      ga,     pa);
            cp16(da + 16, ga + 8, pa);
            const __half* gb = Bm + (long)(col0 + lr) * ldb + k0 + lqh;
            unsigned db = smem_u32(Bsm + st * STAGE_WORDS + lr * PAD32 + lqw);
            cp16(db,      gb,     true);
            cp16(db + 16, gb + 8, true);
        }
        asm volatile("cp.async.commit_group;\n");
    }

    int s = 0;
    for (int it = 0; it < niter; ++it) {
        asm volatile("cp.async.wait_group 2;\n");
        __syncthreads();

        const int pf = it + STAGES - 1;
        if (pf < niter) {
            int sl = s + STAGES - 1; if (sl >= STAGES) sl -= STAGES;
            const int k0 = pf * BKH;
            const __half* ga = A + (long)(row0 + lr) * lda + k0 + lqh;
            unsigned da = smem_u32(Asm + sl * STAGE_WORDS + lr * PAD32 + lqw);
            bool pa = (row0 + lr) < M;
            cp16(da,      ga,     pa);
            cp16(da + 16, ga + 8, pa);
            const __half* gb = Bm + (long)(col0 + lr) * ldb + k0 + lqh;
            unsigned db = smem_u32(Bsm + sl * STAGE_WORDS + lr * PAD32 + lqw);
            cp16(db,      gb,     true);
            cp16(db + 16, gb + 8, true);
        }
        asm volatile("cp.async.commit_group;\n");

        const unsigned* As = Asm + s * STAGE_WORDS;
        const unsigned* Bs = Bsm + s * STAGE_WORDS;
#pragma unroll
        for (int kk = 0; kk < 2; ++kk) {
            const int kb = kk * 8;       // b32 column base (16 halves)
            unsigned af[4][4], bf[4][2];
#pragma unroll
            for (int mi = 0; mi < 4; ++mi) {
                const unsigned* p = As + (wm + mi * 16 + g) * PAD32 + kb + tg;
                af[mi][0] = p[0];
                af[mi][1] = p[8 * PAD32];
                af[mi][2] = p[4];
                af[mi][3] = p[8 * PAD32 + 4];
            }
#pragma unroll
            for (int ni = 0; ni < 4; ++ni) {
                const unsigned* p = Bs + (wn + ni * 8 + g) * PAD32 + kb + tg;
                bf[ni][0] = p[0];
                bf[ni][1] = p[4];
            }
#pragma unroll
            for (int mi = 0; mi < 4; ++mi)
#pragma unroll
                for (int ni = 0; ni < 4; ++ni)
                    mma_f16(c[mi][ni], af[mi][0], af[mi][1], af[mi][2], af[mi][3],
                            bf[ni][0], bf[ni][1]);
        }
        if (++s >= STAGES) s = 0;
    }

    // ---- epilogue ----
#pragma unroll
    for (int mi = 0; mi < 4; ++mi) {
#pragma unroll
        for (int half = 0; half < 2; ++half) {
            int r = row0 + wm + mi * 16 + g + half * 8;
            if (r < M) {
#pragma unroll
                for (int ni = 0; ni < 4; ++ni) {
                    long off = (long)r * ldc + col0 + wn + ni * 8 + tg * 2;
                    float2 v;
                    v.x = c[mi][ni][half * 2 + 0];
                    v.y = c[mi][ni][half * 2 + 1];
                    if (resid) {
                        float2 rr = *(const float2*)(resid + off);
                        v.x += rr.x; v.y += rr.y;
                    }
                    *(float2*)(C + off) = v;
                }
            }
        }
    }
}

// ---- generic batched (scores causal / O-proj / shared-down)
template <bool CAUSAL>
__global__ __launch_bounds__(256, 2)
void hgemm_bat(
    const __half* __restrict__ A, const __half* __restrict__ Bm,
    float* __restrict__ C, const float* __restrict__ resid,
    int M, int K, int lda, int ldb, int ldc,
    long sA, long sB, long sC)
{
    int z = blockIdx.z;
    if (CAUSAL) {
        if (blockIdx.x > blockIdx.y) return;   // tiles strictly above diagonal
    }
    hgemm_body(A + (long)z * sA, Bm + (long)z * sB, C + (long)z * sC,
               resid, M, K, lda, ldb, ldc);
}

// ---- fused Q/K/V projection
__global__ __launch_bounds__(256, 2)
void hqkv_k(const __half* __restrict__ xn,
            float* __restrict__ qt, float* __restrict__ kt, float* __restrict__ vt)
{
    int z = blockIdx.z;
    const __half* B = (z == 0) ? h_qw : (z == 1) ? h_kw : h_vw;
    float* C        = (z == 0) ? qt   : (z == 1) ? kt   : vt;
    hgemm_body(xn, B, C, nullptr, NT, NHID, NHID, NHID, NHID);
}

// ---- PV with split-K: z = head*PVSPLIT + chunk
__global__ __launch_bounds__(256, 2)
void hpv_k(const __half* __restrict__ pr, const __half* __restrict__ vrT,
           float* __restrict__ pvp)
{
    int z = blockIdx.z;
    int head = z >> 2, chunk = z & 3;
    hgemm_body(pr  + (long)head * NS * NS    + chunk * PVK,
               vrT + (long)head * DHEAD * NS + chunk * PVK,
               pvp + (long)chunk * NT * NHID
                   + (long)(head >> 3) * NS * NHID + (head & 7) * DHEAD,
               nullptr, NS, PVK, NS, NS, NHID);
}

// ---- fused shared-MLP gate+up
__global__ __launch_bounds__(256, 2)
void hshup_k(const __half* __restrict__ xn,
             float* __restrict__ gs, float* __restrict__ us)
{
    int z = blockIdx.z;
    hgemm_body(xn, z ? h_su : h_sg, z ? us : gs, nullptr,
               NT, NHID, NHID, NHID, NSI);
}

// ---- fused MoE gate+up grouped: z = 2*e + which
__global__ __launch_bounds__(256, 2)
void hmoeup_k(const __half* __restrict__ xg,
              float* __restrict__ gb, float* __restrict__ ub)
{
    int z = blockIdx.z;
    int e = z >> 1;
    int M = d_cnt[e];
    int off = d_off[e];
    const __half* B = (z & 1) ? h_eu : h_eg;
    float* C        = (z & 1) ? ub : gb;
    hgemm_body(xg + (long)off * NHID, B + (long)e * NMI * NHID,
               C + (long)off * NMI, nullptr, M, NHID, NHID, NHID, NMI);
}

// ---- MoE down grouped
__global__ __launch_bounds__(256, 2)
void hmoedn_k(const __half* __restrict__ gb, float* __restrict__ yb)
{
    int e = blockIdx.z;
    int M = d_cnt[e];
    int off = d_off[e];
    hgemm_body(gb + (long)off * NMI, h_ed + (long)e * NHID * NMI,
               yb + (long)off * NHID, nullptr, M, NMI, NMI, NMI, NHID);
}

// ---------------------------------------------------------------------------
// weight conversion fp32 -> fp16 (RN)
// ---------------------------------------------------------------------------
__global__ void convw_k(const float* __restrict__ src, __half* __restrict__ dst,
                        int n4)
{
    int i = (blockIdx.x * 256 + threadIdx.x);
    if (i < n4) {
        float4 v = *(const float4*)(src + 4 * (long)i);
        __half2 h0 = __floats2half2_rn(v.x, v.y);
        __half2 h1 = __floats2half2_rn(v.z, v.w);
        *(__half2*)(dst + 4 * (long)i)     = h0;
        *(__half2*)(dst + 4 * (long)i + 2) = h1;
    }
}

// ---------------------------------------------------------------------------
// Elementwise / reduction kernels
// ---------------------------------------------------------------------------
// rmsnorm: writes half (GEMM input); optionally fp32 (for gating)
__global__ void rmsnorm_k(const float* __restrict__ x,
                          const float* __restrict__ w,
                          __half* __restrict__ oh, float* __restrict__ o32)
{
    int t = blockIdx.x;
    const float* xr = x + (long)t * NHID;
    __shared__ float red[256];
    float s = 0.f;
    for (int i = threadIdx.x; i < NHID; i += 256) { float v = xr[i]; s += v * v; }
    red[threadIdx.x] = s;
    __syncthreads();
    for (int st = 128; st > 0; st >>= 1) {
        if (threadIdx.x < st) red[threadIdx.x] += red[threadIdx.x + st];
        __syncthreads();
    }
    float scale = rsqrtf(red[0] / (float)NHID + 1e-6f);
    for (int i = threadIdx.x; i < NHID; i += 256) {
        float v = xr[i] * scale * w[i];
        oh[(long)t * NHID + i] = __float2half_rn(v);
        if (o32) o32[(long)t * NHID + i] = v;
    }
}

// RoPE on q,k + scale q; layouts: q,k -> (B,NH,S,HD) half, v -> (B,NH,HD,S) half
__global__ void rope_k(const float* __restrict__ qt, const float* __restrict__ kt,
                       const float* __restrict__ vt,
                       const float* __restrict__ cosp, const float* __restrict__ sinp,
                       __half* __restrict__ qr, __half* __restrict__ kr,
                       __half* __restrict__ vrT)
{
    int t = blockIdx.x;                // token
    int n = blockIdx.y;                // head
    int d = threadIdx.x;               // 0..63
    int b = t / NS, s = t % NS;
    long src = (long)t * NHID + n * DHEAD;
    long dst = ((long)(b * NHEAD + n) * NS + s) * DHEAD;
    long bhv = (long)(b * NHEAD + n) * DHEAD * NS;
    float c  = cosp[s * DHEAD + d];
    float sn = sinp[s * DHEAD + d];
    const float inv = 0.08838834764831845f;  // 1/sqrt(128)

    float q0 = qt[src + d], q1 = qt[src + d + 64];
    qr[dst + d]      = __float2half_rn((q0 * c - q1 * sn) * inv);
    qr[dst + d + 64] = __float2half_rn((q1 * c + q0 * sn) * inv);

    float k0 = kt[src + d], k1 = kt[src + d + 64];
    kr[dst + d]      = __float2half_rn(k0 * c - k1 * sn);
    kr[dst + d + 64] = __float2half_rn(k1 * c + k0 * sn);

    vrT[bhv + (long)d * NS + s]        = __float2half_rn(vt[src + d]);
    vrT[bhv + (long)(d + 64) * NS + s] = __float2half_rn(vt[src + d + 64]);
}

// causal softmax: fp32 scores in, half probs out (zeros beyond diagonal)
__global__ void softmax_causal_k(const float* __restrict__ sc,
                                 __half* __restrict__ pr)
{
    int q  = blockIdx.x;
    int bh = blockIdx.y;
    const float* row = sc + (long)bh * NS * NS + (long)q * NS;
    __half* prow     = pr + (long)bh * NS * NS + (long)q * NS;
    int len = q + 1;
    __shared__ float red[256];
    int tid = threadIdx.x;

    float m = -1e30f;
    for (int i = tid; i < len; i += 256) m = fmaxf(m, row[i]);
    red[tid] = m;
    __syncthreads();
    for (int st = 128; st > 0; st >>= 1) {
        if (tid < st) red[tid] = fmaxf(red[tid], red[tid + st]);
        __syncthreads();
    }
    m = red[0];
    __syncthreads();

    float s = 0.f;
    for (int i = tid; i < len; i += 256) s += expf(row[i] - m);
    red[tid] = s;
    __syncthreads();
    for (int st = 128; st > 0; st >>= 1) {
        if (tid < st) red[tid] += red[tid + st];
        __syncthreads();
    }
    float invs = 1.f / red[0];
    for (int i = tid; i < NS; i += 256) {
        float p = (i < len) ? expf(row[i] - m) * invs : 0.f;
        prow[i] = __float2half_rn(p);
    }
}

__global__ void zero_cnt_k() { if (threadIdx.x < NEXP) d_cnt[threadIdx.x] = 0; }

__global__ void gate_k(const float* __restrict__ xn, const float* __restrict__ gw)
{
    int t = blockIdx.x;
    int tid = threadIdx.x, w = tid >> 5, lane = tid & 31;
    const float* xr = xn + (long)t * NHID;
    const float* gr = gw + (long)w * NHID;
    float s = 0.f;
    for (int i = lane; i < NHID; i += 32) s += xr[i] * gr[i];
    for (int o = 16; o; o >>= 1) s += __shfl_xor_sync(0xffffffffu, s, o);
    __shared__ float lg[NEXP];
    if (lane == 0) lg[w] = s;
    __syncthreads();
    if (tid == 0) {
        float mx = lg[0];
        for (int e = 1; e < NEXP; ++e) mx = fmaxf(mx, lg[e]);
        float p[NEXP];
        for (int e = 0; e < NEXP; ++e) p[e] = expf(lg[e] - mx);
        int e0 = 0; float b0 = p[0];
        for (int e = 1; e < NEXP; ++e) if (p[e] > b0) { b0 = p[e]; e0 = e; }
        int e1 = -1; float b1 = -1.f;
        for (int e = 0; e < NEXP; ++e)
            if (e != e0 && p[e] > b1) { b1 = p[e]; e1 = e; }
        float denom = b0 + b1;
        d_e0[t] = e0; d_e1[t] = e1;
        d_w0[t] = b0 / denom; d_w1[t] = b1 / denom;
        d_r0[t] = atomicAdd(&d_cnt[e0], 1);
        d_r1[t] = atomicAdd(&d_cnt[e1], 1);
    }
}

__global__ void scan_k()
{
    if (threadIdx.x == 0) {
        int a = 0;
        for (int e = 0; e < NEXP; ++e) { d_off[e] = a; a += d_cnt[e]; }
    }
}

// gather half xn rows into expert-sorted slots
__global__ void gather_k(const __half* __restrict__ xnh)
{
    int t = blockIdx.x;
    __shared__ int ss[2];
    if (threadIdx.x == 0) {
        int s0 = d_off[d_e0[t]] + d_r0[t];
        int s1 = d_off[d_e1[t]] + d_r1[t];
        d_s0[t] = s0; d_s1[t] = s1;
        ss[0] = s0; ss[1] = s1;
    }
    __syncthreads();
    const uint4* src = (const uint4*)(xnh + (long)t * NHID);
    uint4* dst0 = (uint4*)(h_xg + (long)ss[0] * NHID);
    uint4* dst1 = (uint4*)(h_xg + (long)ss[1] * NHID);
    for (int i = threadIdx.x; i < NHID / 8; i += 256) {
        uint4 v = src[i];
        dst0[i] = v;
        dst1[i] = v;
    }
}

// silu(g)*u -> half out
__global__ void silumul_k(const float* __restrict__ g, const float* __restrict__ u,
                          __half* __restrict__ o, long n)
{
    long i = (long)blockIdx.x * 256 + threadIdx.x;
    if (i < n) {
        float gv = g[i];
        float s = 1.f / (1.f + expf(-gv));
        o[i] = __float2half_rn(gv * s * u[i]);
    }
}

// reduce PV partials -> half ctx
__global__ void pvred_k(const float* __restrict__ pvp, __half* __restrict__ ctx)
{
    long i = (long)blockIdx.x * 256 + threadIdx.x;
    const long P = (long)NT * NHID;
    float v = pvp[i] + pvp[i + P] + pvp[i + 2 * P] + pvp[i + 3 * P];
    ctx[i] = __float2half_rn(v);
}

// out = x1 + sh + routed
__global__ void combine_k(const float* __restrict__ x1,
                          const float* __restrict__ sh,
                          float* __restrict__ out)
{
    int t = blockIdx.x;
    float w0 = d_w0[t], w1 = d_w1[t];
    long o0 = (long)d_s0[t] * NHID;
    long o1 = (long)d_s1[t] * NHID;
    for (int i = threadIdx.x; i < NHID; i += 256) {
        long idx = (long)t * NHID + i;
        out[idx] = x1[idx] + sh[idx] + w0 * d_ybuf[o0 + i] + w1 * d_ybuf[o1 + i];
    }
}

// ---------------------------------------------------------------------------
// Launch
// ---------------------------------------------------------------------------
static inline void conv(const float* s, __half* d, long n)
{
    int n4 = (int)(n / 4);
    convw_k<<<(n4 + 255) / 256, 256>>>(s, d, n4);
}

extern "C" void kernel_launch(void* const* d_in, const int* in_sizes, int n_in,
                              void* d_out, int out_size)
{
    (void)in_sizes; (void)n_in; (void)out_size;

    const float* hs   = (const float*)d_in[0];
    const float* ln1  = (const float*)d_in[1];
    const float* ln2  = (const float*)d_in[2];
    const float* q_w  = (const float*)d_in[3];
    const float* k_w  = (const float*)d_in[4];
    const float* v_w  = (const float*)d_in[5];
    const float* o_w  = (const float*)d_in[6];
    const float* cosp = (const float*)d_in[7];
    const float* sinp = (const float*)d_in[8];
    const float* gate = (const float*)d_in[9];
    const float* eg   = (const float*)d_in[10];
    const float* eu   = (const float*)d_in[11];
    const float* ed   = (const float*)d_in[12];
    const float* sg   = (const float*)d_in[13];
    const float* su   = (const float*)d_in[14];
    const float* sd   = (const float*)d_in[15];
    float* out = (float*)d_out;

    float *xn32, *qt, *kt, *vt, *sc, *pvp, *x1, *gb, *ub, *yb, *gs, *us, *sh;
    __half *hqw, *hkw, *hvw, *how, *heg, *heu, *hed, *hsg, *hsu, *hsd;
    __half *hxn, *hqr, *hkr, *hvrT, *hpr, *hctx, *hxg, *hgb, *hgs;
    cudaGetSymbolAddress((void**)&xn32, d_xn32);
    cudaGetSymbolAddress((void**)&qt,  d_qt);
    cudaGetSymbolAddress((void**)&kt,  d_kt);
    cudaGetSymbolAddress((void**)&vt,  d_vt);
    cudaGetSymbolAddress((void**)&sc,  d_scores);
    cudaGetSymbolAddress((void**)&pvp, d_pvp);
    cudaGetSymbolAddress((void**)&x1,  d_x1);
    cudaGetSymbolAddress((void**)&gb,  d_gbuf);
    cudaGetSymbolAddress((void**)&ub,  d_ubuf);
    cudaGetSymbolAddress((void**)&yb,  d_ybuf);
    cudaGetSymbolAddress((void**)&gs,  d_gs);
    cudaGetSymbolAddress((void**)&us,  d_us);
    cudaGetSymbolAddress((void**)&sh,  d_sh);
    cudaGetSymbolAddress((void**)&hqw, h_qw);
    cudaGetSymbolAddress((void**)&hkw, h_kw);
    cudaGetSymbolAddress((void**)&hvw, h_vw);
    cudaGetSymbolAddress((void**)&how, h_ow);
    cudaGetSymbolAddress((void**)&heg, h_eg);
    cudaGetSymbolAddress((void**)&heu, h_eu);
    cudaGetSymbolAddress((void**)&hed, h_ed);
    cudaGetSymbolAddress((void**)&hsg, h_sg);
    cudaGetSymbolAddress((void**)&hsu, h_su);
    cudaGetSymbolAddress((void**)&hsd, h_sd);
    cudaGetSymbolAddress((void**)&hxn, h_xn);
    cudaGetSymbolAddress((void**)&hqr, h_qr);
    cudaGetSymbolAddress((void**)&hkr, h_kr);
    cudaGetSymbolAddress((void**)&hvrT, h_vrT);
    cudaGetSymbolAddress((void**)&hpr, h_probs);
    cudaGetSymbolAddress((void**)&hctx, h_ctx);
    cudaGetSymbolAddress((void**)&hxg, h_xg);
    cudaGetSymbolAddress((void**)&hgb, h_gb);
    cudaGetSymbolAddress((void**)&hgs, h_gs);

    cudaFuncSetAttribute(hgemm_bat<false>,
        cudaFuncAttributeMaxDynamicSharedMemorySize, SMEM_BYTES);
    cudaFuncSetAttribute(hgemm_bat<true>,
        cudaFuncAttributeMaxDynamicSharedMemorySize, SMEM_BYTES);
    cudaFuncSetAttribute(hqkv_k,
        cudaFuncAttributeMaxDynamicSharedMemorySize, SMEM_BYTES);
    cudaFuncSetAttribute(hpv_k,
        cudaFuncAttributeMaxDynamicSharedMemorySize, SMEM_BYTES);
    cudaFuncSetAttribute(hshup_k,
        cudaFuncAttributeMaxDynamicSharedMemorySize, SMEM_BYTES);
    cudaFuncSetAttribute(hmoeup_k,
        cudaFuncAttributeMaxDynamicSharedMemorySize, SMEM_BYTES);
    cudaFuncSetAttribute(hmoedn_k,
        cudaFuncAttributeMaxDynamicSharedMemorySize, SMEM_BYTES);

    const long PLANE = (long)NT * NHID;

    // ---- weight conversions ----
    conv(q_w, hqw, (long)NHID * NHID);
    conv(k_w, hkw, (long)NHID * NHID);
    conv(v_w, hvw, (long)NHID * NHID);
    conv(o_w, how, (long)NHID * NHID);
    conv(eg, heg, (long)NEXP * NMI * NHID);
    conv(eu, heu, (long)NEXP * NMI * NHID);
    conv(ed, hed, (long)NEXP * NHID * NMI);
    conv(sg, hsg, (long)NSI * NHID);
    conv(su, hsu, (long)NSI * NHID);
    conv(sd, hsd, (long)NHID * NSI);

    const dim3 gQKV(NHID / BN, NT / BM, 3);          // (8,16,3)
    const dim3 gScore(NS / BN, NS / BM, NB * NHEAD); // (8,8,16)
    const dim3 gPV(1, NS / BM, NB * NHEAD * PVSPLIT);// (1,8,64)
    const dim3 gProj(NHID / BN, NT / BM);            // (8,16)
    const dim3 gShUp(NSI / BN, NT / BM, 2);          // (16,16,2)
    const dim3 gMoeUp(NMI / BN, NSLOT / BM, 2 * NEXP);
    const dim3 gMoeDn(NHID / BN, NSLOT / BM, NEXP);

    // ---- attention ----
    rmsnorm_k<<<NT, 256>>>(hs, ln1, hxn, nullptr);
    hqkv_k<<<gQKV, 256, SMEM_BYTES>>>(hxn, qt, kt, vt);
    rope_k<<<dim3(NT, NHEAD), 64>>>(qt, kt, vt, cosp, sinp, hqr, hkr, hvrT);

    hgemm_bat<true><<<gScore, 256, SMEM_BYTES>>>(hqr, hkr, sc, nullptr,
        NS, DHEAD, DHEAD, DHEAD, NS,
        (long)NS * DHEAD, (long)NS * DHEAD, (long)NS * NS);
    softmax_causal_k<<<dim3(NS, NB * NHEAD), 256>>>(sc, hpr);
    hpv_k<<<gPV, 256, SMEM_BYTES>>>(hpr, hvrT, pvp);
    pvred_k<<<(unsigned)(PLANE / 256), 256>>>(pvp, hctx);
    hgemm_bat<false><<<gProj, 256, SMEM_BYTES>>>(hctx, how, x1, hs,
        NT, NHID, NHID, NHID, NHID, 0, 0, 0);

    // ---- MoE ----
    rmsnorm_k<<<NT, 256>>>(x1, ln2, hxn, xn32);
    zero_cnt_k<<<1, 32>>>();
    gate_k<<<NT, 256>>>(xn32, gate);
    scan_k<<<1, 1>>>();
    gather_k<<<NT, 256>>>(hxn);

    hmoeup_k<<<gMoeUp, 256, SMEM_BYTES>>>(hxg, gb, ub);
    silumul_k<<<(unsigned)(((long)NSLOT * NMI + 255) / 256), 256>>>(
        gb, ub, hgb, (long)NSLOT * NMI);
    hmoedn_k<<<gMoeDn, 256, SMEM_BYTES>>>(hgb, yb);

    // ---- shared MLP ----
    hshup_k<<<gShUp, 256, SMEM_BYTES>>>(hxn, gs, us);
    silumul_k<<<(unsigned)(((long)NT * NSI + 255) / 256), 256>>>(
        gs, us, hgs, (long)NT * NSI);
    hgemm_bat<false><<<gProj, 256, SMEM_BYTES>>>(hgs, hsd, sh, nullptr,
        NT, NSI, NSI, NSI, NHID, 0, 0, 0);

    // ---- combine ----
    combine_k<<<NT, 256>>>(x1, sh, out);
}

// round 8
// speedup vs baseline: 1.5844x; 1.1506x over previous
#include <cuda_runtime.h>
#include <cuda_fp16.h>
#include <math.h>

// ---------------------------------------------------------------------------
// Problem constants
// ---------------------------------------------------------------------------
namespace {
constexpr int NB = 2, NS = 1024, NHID = 1024, NHEAD = 8, DHEAD = 128;
constexpr int NEXP = 8, NMI = 1024, NSI = 2048;
constexpr int NT = NB * NS;          // 2048 tokens
constexpr int NSLOT = 2 * NT;        // 4096 expert slots (top-2)

// fp16 GEMM tile: 128x128x32(halves), 8 warps of 64x32, 4-stage cp.async
constexpr int BM = 128, BN = 128, BKH = 32;     // BKH halves per k-iter
constexpr int PAD32 = 20;                        // row stride in b32 (80B)
constexpr int STAGES = 4;
constexpr int STAGE_WORDS = BM * PAD32;          // 2560 b32 per tile-stage
constexpr int SMEM_BYTES = 2 * STAGES * STAGE_WORDS * 4;   // 81920

constexpr int PVSPLIT = 4;
constexpr int PVK = NS / PVSPLIT;    // 256
}

// ---------------------------------------------------------------------------
// Static device scratch (no allocations allowed)
// ---------------------------------------------------------------------------
// fp32 buffers
__device__ float d_xn32[NT * NHID];                      // for gating (fp32 path)
__device__ float d_qt[NT * NHID];
__device__ float d_kt[NT * NHID];
__device__ float d_vt[NT * NHID];
__device__ float d_scores[(long)NB * NHEAD * NS * NS];   // 64 MB (QK^T out)
__device__ float d_pvp[(long)PVSPLIT * NT * NHID];       // PV split-K partials
__device__ float d_x1[NT * NHID];
__device__ float d_gbuf[NSLOT * NMI];
__device__ float d_ubuf[NSLOT * NMI];
__device__ float d_ybuf[NSLOT * NHID];
__device__ float d_gs[NT * NSI];
__device__ float d_us[NT * NSI];
__device__ float d_sh[NT * NHID];
// fp16 buffers (GEMM operands)
__device__ __half h_qw[NHID * NHID];
__device__ __half h_kw[NHID * NHID];
__device__ __half h_vw[NHID * NHID];
__device__ __half h_ow[NHID * NHID];
__device__ __half h_eg[NEXP * NMI * NHID];
__device__ __half h_eu[NEXP * NMI * NHID];
__device__ __half h_ed[NEXP * NHID * NMI];
__device__ __half h_sg[NSI * NHID];
__device__ __half h_su[NSI * NHID];
__device__ __half h_sd[NHID * NSI];
__device__ __half h_xn[NT * NHID];
__device__ __half h_qr[NT * NHID];    // (B,NH,S,HD)
__device__ __half h_kr[NT * NHID];    // (B,NH,S,HD)
__device__ __half h_vrT[NT * NHID];   // (B,NH,HD,S)
__device__ __half h_probs[(long)NB * NHEAD * NS * NS];   // 32 MB
__device__ __half h_ctx[NT * NHID];
__device__ __half h_xg[NSLOT * NHID];
__device__ __half h_gb[NSLOT * NMI];
__device__ __half h_gs[NT * NSI];
// routing state
__device__ int   d_cnt[NEXP];
__device__ int   d_off[NEXP];
__device__ int   d_e0[NT], d_e1[NT], d_r0[NT], d_r1[NT], d_s0[NT], d_s1[NT];
__device__ float d_w0[NT], d_w1[NT];

// ---------------------------------------------------------------------------
// helpers
// ---------------------------------------------------------------------------
__device__ __forceinline__ unsigned smem_u32(const void* p) {
    return (unsigned)__cvta_generic_to_shared(p);
}

__device__ __forceinline__ void cp16(unsigned dst, const void* src, bool pred) {
    int sz = pred ? 16 : 0;
    asm volatile("cp.async.cg.shared.global [%0], [%1], 16, %2;\n"
                 :: "r"(dst), "l"(src), "r"(sz));
}

__device__ __forceinline__ void ldsm4(unsigned& r0, unsigned& r1,
                                      unsigned& r2, unsigned& r3, unsigned addr)
{
    asm volatile("ldmatrix.sync.aligned.m8n8.x4.shared.b16 {%0,%1,%2,%3}, [%4];"
                 : "=r"(r0), "=r"(r1), "=r"(r2), "=r"(r3) : "r"(addr));
}

__device__ __forceinline__ void mma_f16(float c[4],
    unsigned a0, unsigned a1, unsigned a2, unsigned a3,
    unsigned b0, unsigned b1)
{
    asm volatile(
        "mma.sync.aligned.m16n8k16.row.col.f32.f16.f16.f32 "
        "{%0,%1,%2,%3}, {%4,%5,%6,%7}, {%8,%9}, {%0,%1,%2,%3};\n"
        : "+f"(c[0]), "+f"(c[1]), "+f"(c[2]), "+f"(c[3])
        : "r"(a0), "r"(a1), "r"(a2), "r"(a3), "r"(b0), "r"(b1));
}

// ---------------------------------------------------------------------------
// FP16 tensor-core GEMM:  C[M,N] = A[M,K] * B^T  (B stored (N,K) row-major,
// all element offsets/lds in HALVES).  128x128 block, 8 warps of 64x32
// (4x4 m16n8k16), 4-stage cp.async, ldmatrix operand loads.
// M may be ragged (zfill + store guards). N mult of 128, K mult of 32.
// ---------------------------------------------------------------------------
__device__ __forceinline__ void hgemm_body(
    const __half* __restrict__ A, const __half* __restrict__ Bm,
    float* __restrict__ C, const float* __restrict__ resid,
    int M, int K, int lda, int ldb, int ldc)
{
    extern __shared__ unsigned smu[];
    unsigned* Asm = smu;                         // [STAGES][BM][PAD32]
    unsigned* Bsm = smu + STAGES * STAGE_WORDS;

    const int tid  = threadIdx.x;
    const int wid  = tid >> 5;
    const int lane = tid & 31;
    const int g    = lane >> 2;          // 0..7
    const int tg   = lane & 3;           // 0..3
    const int wm   = (wid & 1) * 64;
    const int wn   = (wid >> 1) * 32;
    const int row0 = blockIdx.y * BM;
    const int col0 = blockIdx.x * BN;
    if (row0 >= M) return;

    // ldmatrix per-thread address components (rows / b32 words)
    const int rA = (lane & 7) + ((lane >> 3) & 1) * 8;   // A row within 16
    const int cA = ((lane >> 4) & 1) * 4;                // A k-word offset
    const int rB = (lane & 7) + ((lane >> 4) & 1) * 8;   // B row within 16
    const int cB = ((lane >> 3) & 1) * 4;                // B k-word offset

    float c[4][4][4];
#pragma unroll
    for (int mi = 0; mi < 4; ++mi)
#pragma unroll
        for (int ni = 0; ni < 4; ++ni)
#pragma unroll
            for (int r = 0; r < 4; ++r) c[mi][ni][r] = 0.f;

    const int lr = tid >> 1;             // 0..127  (row within tile)
    const int lqh = (tid & 1) * 16;      // half-offset 0/16
    const int lqw = (tid & 1) * 8;       // b32-offset 0/8
    const int niter = K / BKH;

    // ---- prologue: stages 0..2 ----
#pragma unroll
    for (int st = 0; st < STAGES - 1; ++st) {
        if (st < niter) {
            const int k0 = st * BKH;
            const __half* ga = A + (long)(row0 + lr) * lda + k0 + lqh;
            unsigned da = smem_u32(Asm + st * STAGE_WORDS + lr * PAD32 + lqw);
            bool pa = (row0 + lr) < M;
            cp16(da,      ga,     pa);
            cp16(da + 16, ga + 8, pa);
            const __half* gb = Bm + (long)(col0 + lr) * ldb + k0 + lqh;
            unsigned db = smem_u32(Bsm + st * STAGE_WORDS + lr * PAD32 + lqw);
            cp16(db,      gb,     true);
            cp16(db + 16, gb + 8, true);
        }
        asm volatile("cp.async.commit_group;\n");
    }

    int s = 0;
    for (int it = 0; it < niter; ++it) {
        asm volatile("cp.async.wait_group 2;\n");
        __syncthreads();

        const int pf = it + STAGES - 1;
        if (pf < niter) {
            int sl = s + STAGES - 1; if (sl >= STAGES) sl -= STAGES;
            const int k0 = pf * BKH;
            const __half* ga = A + (long)(row0 + lr) * lda + k0 + lqh;
            unsigned da = smem_u32(Asm + sl * STAGE_WORDS + lr * PAD32 + lqw);
            bool pa = (row0 + lr) < M;
            cp16(da,      ga,     pa);
            cp16(da + 16, ga + 8, pa);
            const __half* gb = Bm + (long)(col0 + lr) * ldb + k0 + lqh;
            unsigned db = smem_u32(Bsm + sl * STAGE_WORDS + lr * PAD32 + lqw);
            cp16(db,      gb,     true);
            cp16(db + 16, gb + 8, true);
        }
        asm volatile("cp.async.commit_group;\n");

        const unsigned a_base = smem_u32(Asm + s * STAGE_WORDS);
        const unsigned b_base = smem_u32(Bsm + s * STAGE_WORDS);
#pragma unroll
        for (int kk = 0; kk < 2; ++kk) {
            const int kb = kk * 8;       // b32 column base (16 halves)
            unsigned af[4][4], bf[4][2];
#pragma unroll
            for (int mi = 0; mi < 4; ++mi) {
                unsigned addr = a_base +
                    4u * ((wm + mi * 16 + rA) * PAD32 + kb + cA);
                ldsm4(af[mi][0], af[mi][1], af[mi][2], af[mi][3], addr);
            }
#pragma unroll
            for (int p = 0; p < 2; ++p) {
                unsigned addr = b_base +
                    4u * ((wn + p * 16 + rB) * PAD32 + kb + cB);
                ldsm4(bf[2 * p][0], bf[2 * p][1],
                      bf[2 * p + 1][0], bf[2 * p + 1][1], addr);
            }
#pragma unroll
            for (int mi = 0; mi < 4; ++mi)
#pragma unroll
                for (int ni = 0; ni < 4; ++ni)
                    mma_f16(c[mi][ni], af[mi][0], af[mi][1], af[mi][2], af[mi][3],
                            bf[ni][0], bf[ni][1]);
        }
        if (++s >= STAGES) s = 0;
    }

    // ---- epilogue ----
#pragma unroll
    for (int mi = 0; mi < 4; ++mi) {
#pragma unroll
        for (int half = 0; half < 2; ++half) {
            int r = row0 + wm + mi * 16 + g + half * 8;
            if (r < M) {
#pragma unroll
                for (int ni = 0; ni < 4; ++ni) {
                    long off = (long)r * ldc + col0 + wn + ni * 8 + tg * 2;
                    float2 v;
                    v.x = c[mi][ni][half * 2 + 0];
                    v.y = c[mi][ni][half * 2 + 1];
                    if (resid) {
                        float2 rr = *(const float2*)(resid + off);
                        v.x += rr.x; v.y += rr.y;
                    }
                    *(float2*)(C + off) = v;
                }
            }
        }
    }
}

// ---- generic batched (scores causal / O-proj / shared-down)
template <bool CAUSAL>
__global__ __launch_bounds__(256, 2)
void hgemm_bat(
    const __half* __restrict__ A, const __half* __restrict__ Bm,
    float* __restrict__ C, const float* __restrict__ resid,
    int M, int K, int lda, int ldb, int ldc,
    long sA, long sB, long sC)
{
    int z = blockIdx.z;
    if (CAUSAL) {
        if (blockIdx.x > blockIdx.y) return;   // tiles strictly above diagonal
    }
    hgemm_body(A + (long)z * sA, Bm + (long)z * sB, C + (long)z * sC,
               resid, M, K, lda, ldb, ldc);
}

// ---- fused Q/K/V projection
__global__ __launch_bounds__(256, 2)
void hqkv_k(const __half* __restrict__ xn,
            float* __restrict__ qt, float* __restrict__ kt, float* __restrict__ vt)
{
    int z = blockIdx.z;
    const __half* B = (z == 0) ? h_qw : (z == 1) ? h_kw : h_vw;
    float* C        = (z == 0) ? qt   : (z == 1) ? kt   : vt;
    hgemm_body(xn, B, C, nullptr, NT, NHID, NHID, NHID, NHID);
}

// ---- PV with split-K: z = head*PVSPLIT + chunk; causal block skip
__global__ __launch_bounds__(256, 2)
void hpv_k(const __half* __restrict__ pr, const __half* __restrict__ vrT,
           float* __restrict__ pvp)
{
    int z = blockIdx.z;
    int head = z >> 2, chunk = z & 3;
    // queries row0..row0+127; chunk covers keys [chunk*256, +255]; skip when
    // entirely above the diagonal (probs all zero; pvred excludes the plane).
    if (2 * chunk > (int)blockIdx.y) return;
    hgemm_body(pr  + (long)head * NS * NS    + chunk * PVK,
               vrT + (long)head * DHEAD * NS + chunk * PVK,
               pvp + (long)chunk * NT * NHID
                   + (long)(head >> 3) * NS * NHID + (head & 7) * DHEAD,
               nullptr, NS, PVK, NS, NS, NHID);
}

// ---- fused shared-MLP gate+up
__global__ __launch_bounds__(256, 2)
void hshup_k(const __half* __restrict__ xn,
             float* __restrict__ gs, float* __restrict__ us)
{
    int z = blockIdx.z;
    hgemm_body(xn, z ? h_su : h_sg, z ? us : gs, nullptr,
               NT, NHID, NHID, NHID, NSI);
}

// ---- fused MoE gate+up grouped: z = 2*e + which
__global__ __launch_bounds__(256, 2)
void hmoeup_k(const __half* __restrict__ xg,
              float* __restrict__ gb, float* __restrict__ ub)
{
    int z = blockIdx.z;
    int e = z >> 1;
    int M = d_cnt[e];
    int off = d_off[e];
    const __half* B = (z & 1) ? h_eu : h_eg;
    float* C        = (z & 1) ? ub : gb;
    hgemm_body(xg + (long)off * NHID, B + (long)e * NMI * NHID,
               C + (long)off * NMI, nullptr, M, NHID, NHID, NHID, NMI);
}

// ---- MoE down grouped
__global__ __launch_bounds__(256, 2)
void hmoedn_k(const __half* __restrict__ gb, float* __restrict__ yb)
{
    int e = blockIdx.z;
    int M = d_cnt[e];
    int off = d_off[e];
    hgemm_body(gb + (long)off * NMI, h_ed + (long)e * NHID * NMI,
               yb + (long)off * NHID, nullptr, M, NMI, NMI, NMI, NHID);
}

// ---------------------------------------------------------------------------
// fused weight conversion fp32 -> fp16 (one launch, segment ladder, float4s)
// ---------------------------------------------------------------------------
namespace {
constexpr int W1 = NHID * NHID / 4;             // 262144 (q/k/v/o)
constexpr int WE = NEXP * NMI * NHID / 4;       // 2097152 (eg/eu/ed)
constexpr int WS = NSI * NHID / 4;              // 524288 (sg/su/sd)
constexpr int CONV_TOT = 4 * W1 + 3 * WE + 3 * WS;   // 8912896
}

__global__ void conv_all_k(
    const float* __restrict__ qw, const float* __restrict__ kw,
    const float* __restrict__ vw, const float* __restrict__ ow,
    const float* __restrict__ eg, const float* __restrict__ eu,
    const float* __restrict__ ed, const float* __restrict__ sg,
    const float* __restrict__ su, const float* __restrict__ sd)
{
    int i = blockIdx.x * 256 + threadIdx.x;
    if (i >= CONV_TOT) return;
    const float* src; __half* dst; int j = i;
    if      (j < 1 * W1) { src = qw; dst = h_qw; }
    else if (j < 2 * W1) { src = kw; dst = h_kw; j -= 1 * W1; }
    else if (j < 3 * W1) { src = vw; dst = h_vw; j -= 2 * W1; }
    else if (j < 4 * W1) { src = ow; dst = h_ow; j -= 3 * W1; }
    else {
        j -= 4 * W1;
        if      (j < 1 * WE) { src = eg; dst = h_eg; }
        else if (j < 2 * WE) { src = eu; dst = h_eu; j -= 1 * WE; }
        else if (j < 3 * WE) { src = ed; dst = h_ed; j -= 2 * WE; }
        else {
            j -= 3 * WE;
            if      (j < 1 * WS) { src = sg; dst = h_sg; }
            else if (j < 2 * WS) { src = su; dst = h_su; j -= 1 * WS; }
            else                 { src = sd; dst = h_sd; j -= 2 * WS; }
        }
    }
    float4 v = *(const float4*)(src + 4 * (long)j);
    __half2 h0 = __floats2half2_rn(v.x, v.y);
    __half2 h1 = __floats2half2_rn(v.z, v.w);
    *(__half2*)(dst + 4 * (long)j)     = h0;
    *(__half2*)(dst + 4 * (long)j + 2) = h1;
}

// ---------------------------------------------------------------------------
// Elementwise / reduction kernels
// ---------------------------------------------------------------------------
__global__ void rmsnorm_k(const float* __restrict__ x,
                          const float* __restrict__ w,
                          __half* __restrict__ oh, float* __restrict__ o32)
{
    int t = blockIdx.x;
    const float* xr = x + (long)t * NHID;
    __shared__ float red[256];
    float s = 0.f;
    for (int i = threadIdx.x; i < NHID; i += 256) { float v = xr[i]; s += v * v; }
    red[threadIdx.x] = s;
    __syncthreads();
    for (int st = 128; st > 0; st >>= 1) {
        if (threadIdx.x < st) red[threadIdx.x] += red[threadIdx.x + st];
        __syncthreads();
    }
    float scale = rsqrtf(red[0] / (float)NHID + 1e-6f);
    for (int i = threadIdx.x; i < NHID; i += 256) {
        float v = xr[i] * scale * w[i];
        oh[(long)t * NHID + i] = __float2half_rn(v);
        if (o32) o32[(long)t * NHID + i] = v;
    }
}

__global__ void rope_k(const float* __restrict__ qt, const float* __restrict__ kt,
                       const float* __restrict__ vt,
                       const float* __restrict__ cosp, const float* __restrict__ sinp,
                       __half* __restrict__ qr, __half* __restrict__ kr,
                       __half* __restrict__ vrT)
{
    int t = blockIdx.x;                // token
    int n = blockIdx.y;                // head
    int d = threadIdx.x;               // 0..63
    int b = t / NS, s = t % NS;
    long src = (long)t * NHID + n * DHEAD;
    long dst = ((long)(b * NHEAD + n) * NS + s) * DHEAD;
    long bhv = (long)(b * NHEAD + n) * DHEAD * NS;
    float c  = cosp[s * DHEAD + d];
    float sn = sinp[s * DHEAD + d];
    const float inv = 0.08838834764831845f;  // 1/sqrt(128)

    float q0 = qt[src + d], q1 = qt[src + d + 64];
    qr[dst + d]      = __float2half_rn((q0 * c - q1 * sn) * inv);
    qr[dst + d + 64] = __float2half_rn((q1 * c + q0 * sn) * inv);

    float k0 = kt[src + d], k1 = kt[src + d + 64];
    kr[dst + d]      = __float2half_rn(k0 * c - k1 * sn);
    kr[dst + d + 64] = __float2half_rn(k1 * c + k0 * sn);

    vrT[bhv + (long)d * NS + s]        = __float2half_rn(vt[src + d]);
    vrT[bhv + (long)(d + 64) * NS + s] = __float2half_rn(vt[src + d + 64]);
}

__global__ void softmax_causal_k(const float* __restrict__ sc,
                                 __half* __restrict__ pr)
{
    int q  = blockIdx.x;
    int bh = blockIdx.y;
    const float* row = sc + (long)bh * NS * NS + (long)q * NS;
    __half* prow     = pr + (long)bh * NS * NS + (long)q * NS;
    int len = q + 1;
    __shared__ float red[256];
    int tid = threadIdx.x;

    float m = -1e30f;
    for (int i = tid; i < len; i += 256) m = fmaxf(m, row[i]);
    red[tid] = m;
    __syncthreads();
    for (int st = 128; st > 0; st >>= 1) {
        if (tid < st) red[tid] = fmaxf(red[tid], red[tid + st]);
        __syncthreads();
    }
    m = red[0];
    __syncthreads();

    float s = 0.f;
    for (int i = tid; i < len; i += 256) s += expf(row[i] - m);
    red[tid] = s;
    __syncthreads();
    for (int st = 128; st > 0; st >>= 1) {
        if (tid < st) red[tid] += red[tid + st];
        __syncthreads();
    }
    float invs = 1.f / red[0];
    for (int i = tid; i < NS; i += 256) {
        float p = (i < len) ? expf(row[i] - m) * invs : 0.f;
        prow[i] = __float2half_rn(p);
    }
}

__global__ void zero_cnt_k() { if (threadIdx.x < NEXP) d_cnt[threadIdx.x] = 0; }

__global__ void gate_k(const float* __restrict__ xn, const float* __restrict__ gw)
{
    int t = blockIdx.x;
    int tid = threadIdx.x, w = tid >> 5, lane = tid & 31;
    const float* xr = xn + (long)t * NHID;
    const float* gr = gw + (long)w * NHID;
    float s = 0.f;
    for (int i = lane; i < NHID; i += 32) s += xr[i] * gr[i];
    for (int o = 16; o; o >>= 1) s += __shfl_xor_sync(0xffffffffu, s, o);
    __shared__ float lg[NEXP];
    if (lane == 0) lg[w] = s;
    __syncthreads();
    if (tid == 0) {
        float mx = lg[0];
        for (int e = 1; e < NEXP; ++e) mx = fmaxf(mx, lg[e]);
        float p[NEXP];
        for (int e = 0; e < NEXP; ++e) p[e] = expf(lg[e] - mx);
        int e0 = 0; float b0 = p[0];
        for (int e = 1; e < NEXP; ++e) if (p[e] > b0) { b0 = p[e]; e0 = e; }
        int e1 = -1; float b1 = -1.f;
        for (int e = 0; e < NEXP; ++e)
            if (e != e0 && p[e] > b1) { b1 = p[e]; e1 = e; }
        float denom = b0 + b1;
        d_e0[t] = e0; d_e1[t] = e1;
        d_w0[t] = b0 / denom; d_w1[t] = b1 / denom;
        d_r0[t] = atomicAdd(&d_cnt[e0], 1);
        d_r1[t] = atomicAdd(&d_cnt[e1], 1);
    }
}

__global__ void scan_k()
{
    if (threadIdx.x == 0) {
        int a = 0;
        for (int e = 0; e < NEXP; ++e) { d_off[e] = a; a += d_cnt[e]; }
    }
}

__global__ void gather_k(const __half* __restrict__ xnh)
{
    int t = blockIdx.x;
    __shared__ int ss[2];
    if (threadIdx.x == 0) {
        int s0 = d_off[d_e0[t]] + d_r0[t];
        int s1 = d_off[d_e1[t]] + d_r1[t];
        d_s0[t] = s0; d_s1[t] = s1;
        ss[0] = s0; ss[1] = s1;
    }
    __syncthreads();
    const uint4* src = (const uint4*)(xnh + (long)t * NHID);
    uint4* dst0 = (uint4*)(h_xg + (long)ss[0] * NHID);
    uint4* dst1 = (uint4*)(h_xg + (long)ss[1] * NHID);
    for (int i = threadIdx.x; i < NHID / 8; i += 256) {
        uint4 v = src[i];
        dst0[i] = v;
        dst1[i] = v;
    }
}

__global__ void silumul_k(const float* __restrict__ g, const float* __restrict__ u,
                          __half* __restrict__ o, long n)
{
    long i = (long)blockIdx.x * 256 + threadIdx.x;
    if (i < n) {
        float gv = g[i];
        float s = 1.f / (1.f + expf(-gv));
        o[i] = __float2half_rn(gv * s * u[i]);
    }
}

// reduce PV partials -> half ctx; only chunks at-or-below the diagonal count
__global__ void pvred_k(const float* __restrict__ pvp, __half* __restrict__ ctx)
{
    long i = (long)blockIdx.x * 256 + threadIdx.x;
    const long P = (long)NT * NHID;
    int s = (int)((i / NHID) % NS);      // query position
    float v = pvp[i];
    if (s >= 1 * PVK) v += pvp[i + P];
    if (s >= 2 * PVK) v += pvp[i + 2 * P];
    if (s >= 3 * PVK) v += pvp[i + 3 * P];
    ctx[i] = __float2half_rn(v);
}

__global__ void combine_k(const float* __restrict__ x1,
                          const float* __restrict__ sh,
                          float* __restrict__ out)
{
    int t = blockIdx.x;
    float w0 = d_w0[t], w1 = d_w1[t];
    long o0 = (long)d_s0[t] * NHID;
    long o1 = (long)d_s1[t] * NHID;
    for (int i = threadIdx.x; i < NHID; i += 256) {
        long idx = (long)t * NHID + i;
        out[idx] = x1[idx] + sh[idx] + w0 * d_ybuf[o0 + i] + w1 * d_ybuf[o1 + i];
    }
}

// ---------------------------------------------------------------------------
// Launch
// ---------------------------------------------------------------------------
extern "C" void kernel_launch(void* const* d_in, const int* in_sizes, int n_in,
                              void* d_out, int out_size)
{
    (void)in_sizes; (void)n_in; (void)out_size;

    const float* hs   = (const float*)d_in[0];
    const float* ln1  = (const float*)d_in[1];
    const float* ln2  = (const float*)d_in[2];
    const float* q_w  = (const float*)d_in[3];
    const float* k_w  = (const float*)d_in[4];
    const float* v_w  = (const float*)d_in[5];
    const float* o_w  = (const float*)d_in[6];
    const float* cosp = (const float*)d_in[7];
    const float* sinp = (const float*)d_in[8];
    const float* gate = (const float*)d_in[9];
    const float* eg   = (const float*)d_in[10];
    const float* eu   = (const float*)d_in[11];
    const float* ed   = (const float*)d_in[12];
    const float* sg   = (const float*)d_in[13];
    const float* su   = (const float*)d_in[14];
    const float* sd   = (const float*)d_in[15];
    float* out = (float*)d_out;

    float *xn32, *qt, *kt, *vt, *sc, *pvp, *x1, *gb, *ub, *yb, *gs, *us, *sh;
    __half *hxn, *hqr, *hkr, *hvrT, *hpr, *hctx, *hxg, *hgb, *hgs, *how2, *hsd2;
    cudaGetSymbolAddress((void**)&xn32, d_xn32);
    cudaGetSymbolAddress((void**)&qt,  d_qt);
    cudaGetSymbolAddress((void**)&kt,  d_kt);
    cudaGetSymbolAddress((void**)&vt,  d_vt);
    cudaGetSymbolAddress((void**)&sc,  d_scores);
    cudaGetSymbolAddress((void**)&pvp, d_pvp);
    cudaGetSymbolAddress((void**)&x1,  d_x1);
    cudaGetSymbolAddress((void**)&gb,  d_gbuf);
    cudaGetSymbolAddress((void**)&ub,  d_ubuf);
    cudaGetSymbolAddress((void**)&yb,  d_ybuf);
    cudaGetSymbolAddress((void**)&gs,  d_gs);
    cudaGetSymbolAddress((void**)&us,  d_us);
    cudaGetSymbolAddress((void**)&sh,  d_sh);
    cudaGetSymbolAddress((void**)&hxn, h_xn);
    cudaGetSymbolAddress((void**)&hqr, h_qr);
    cudaGetSymbolAddress((void**)&hkr, h_kr);
    cudaGetSymbolAddress((void**)&hvrT, h_vrT);
    cudaGetSymbolAddress((void**)&hpr, h_probs);
    cudaGetSymbolAddress((void**)&hctx, h_ctx);
    cudaGetSymbolAddress((void**)&hxg, h_xg);
    cudaGetSymbolAddress((void**)&hgb, h_gb);
    cudaGetSymbolAddress((void**)&hgs, h_gs);
    cudaGetSymbolAddress((void**)&how2, h_ow);
    cudaGetSymbolAddress((void**)&hsd2, h_sd);

    cudaFuncSetAttribute(hgemm_bat<false>,
        cudaFuncAttributeMaxDynamicSharedMemorySize, SMEM_BYTES);
    cudaFuncSetAttribute(hgemm_bat<true>,
        cudaFuncAttributeMaxDynamicSharedMemorySize, SMEM_BYTES);
    cudaFuncSetAttribute(hqkv_k,
        cudaFuncAttributeMaxDynamicSharedMemorySize, SMEM_BYTES);
    cudaFuncSetAttribute(hpv_k,
        cudaFuncAttributeMaxDynamicSharedMemorySize, SMEM_BYTES);
    cudaFuncSetAttribute(hshup_k,
        cudaFuncAttributeMaxDynamicSharedMemorySize, SMEM_BYTES);
    cudaFuncSetAttribute(hmoeup_k,
        cudaFuncAttributeMaxDynamicSharedMemorySize, SMEM_BYTES);
    cudaFuncSetAttribute(hmoedn_k,
        cudaFuncAttributeMaxDynamicSharedMemorySize, SMEM_BYTES);

    const long PLANE = (long)NT * NHID;

    // ---- all weight conversions in one launch ----
    conv_all_k<<<(CONV_TOT + 255) / 256, 256>>>(q_w, k_w, v_w, o_w,
                                                eg, eu, ed, sg, su, sd);

    const dim3 gQKV(NHID / BN, NT / BM, 3);          // (8,16,3)
    const dim3 gScore(NS / BN, NS / BM, NB * NHEAD); // (8,8,16)
    const dim3 gPV(1, NS / BM, NB * NHEAD * PVSPLIT);// (1,8,64)
    const dim3 gProj(NHID / BN, NT / BM);            // (8,16)
    const dim3 gShUp(NSI / BN, NT / BM, 2);          // (16,16,2)
    const dim3 gMoeUp(NMI / BN, NSLOT / BM, 2 * NEXP);
    const dim3 gMoeDn(NHID / BN, NSLOT / BM, NEXP);

    // ---- attention ----
    rmsnorm_k<<<NT, 256>>>(hs, ln1, hxn, nullptr);
    hqkv_k<<<gQKV, 256, SMEM_BYTES>>>(hxn, qt, kt, vt);
    rope_k<<<dim3(NT, NHEAD), 64>>>(qt, kt, vt, cosp, sinp, hqr, hkr, hvrT);

    hgemm_bat<true><<<gScore, 256, SMEM_BYTES>>>(hqr, hkr, sc, nullptr,
        NS, DHEAD, DHEAD, DHEAD, NS,
        (long)NS * DHEAD, (long)NS * DHEAD, (long)NS * NS);
    softmax_causal_k<<<dim3(NS, NB * NHEAD), 256>>>(sc, hpr);
    hpv_k<<<gPV, 256, SMEM_BYTES>>>(hpr, hvrT, pvp);
    pvred_k<<<(unsigned)(PLANE / 256), 256>>>(pvp, hctx);
    hgemm_bat<false><<<gProj, 256, SMEM_BYTES>>>(hctx, how2, x1, hs,
        NT, NHID, NHID, NHID, NHID, 0, 0, 0);

    // ---- MoE ----
    rmsnorm_k<<<NT, 256>>>(x1, ln2, hxn, xn32);
    zero_cnt_k<<<1, 32>>>();
    gate_k<<<NT, 256>>>(xn32, gate);
    scan_k<<<1, 1>>>();
    gather_k<<<NT, 256>>>(hxn);

    hmoeup_k<<<gMoeUp, 256, SMEM_BYTES>>>(hxg, gb, ub);
    silumul_k<<<(unsigned)(((long)NSLOT * NMI + 255) / 256), 256>>>(
        gb, ub, hgb, (long)NSLOT * NMI);
    hmoedn_k<<<gMoeDn, 256, SMEM_BYTES>>>(hgb, yb);

    // ---- shared MLP ----
    hshup_k<<<gShUp, 256, SMEM_BYTES>>>(hxn, gs, us);
    silumul_k<<<(unsigned)(((long)NT * NSI + 255) / 256), 256>>>(
        gs, us, hgs, (long)NT * NSI);
    hgemm_bat<false><<<gProj, 256, SMEM_BYTES>>>(hgs, hsd2, sh, nullptr,
        NT, NSI, NSI, NSI, NHID, 0, 0, 0);

    // ---- combine ----
    combine_k<<<NT, 256>>>(x1, sh, out);
}

// round 9
// speedup vs baseline: 1.7918x; 1.1309x over previous
#include <cuda_runtime.h>
#include <cuda_fp16.h>
#include <math.h>

// ---------------------------------------------------------------------------
// Problem constants
// ---------------------------------------------------------------------------
namespace {
constexpr int NB = 2, NS = 1024, NHID = 1024, NHEAD = 8, DHEAD = 128;
constexpr int NEXP = 8, NMI = 1024, NSI = 2048;
constexpr int NT = NB * NS;          // 2048 tokens
constexpr int NSLOT = 2 * NT;        // 4096 expert slots (top-2)

// fp16 GEMM tile: 128x128x32(halves), 8 warps of 64x32, 4-stage cp.async
constexpr int BM = 128, BN = 128, BKH = 32;
constexpr int PAD32 = 20;                        // row stride in b32 (80B)
constexpr int STAGES = 4;
constexpr int STAGE_WORDS = BM * PAD32;          // 2560 b32 per tile-stage
constexpr int SMEM_BYTES = 2 * STAGES * STAGE_WORDS * 4;   // 81920

// flash attention smem: Q + 2xK + 2xV tiles of 128 rows x 68 words
constexpr int FPW = 68;                          // words per row (136 halves)
constexpr int FTILE_W = 128 * FPW;               // 8704 words per tile
constexpr int FLASH_SMEM = 5 * FTILE_W * 4;      // 174080 bytes
}

// ---------------------------------------------------------------------------
// Static device scratch (no allocations allowed)
// ---------------------------------------------------------------------------
// fp32 buffers
__device__ float d_xn32[NT * NHID];
__device__ float d_x1[NT * NHID];
__device__ float d_gbuf[NSLOT * NMI];
__device__ float d_ubuf[NSLOT * NMI];
__device__ float d_ybuf[NSLOT * NHID];
__device__ float d_gs[NT * NSI];
__device__ float d_us[NT * NSI];
__device__ float d_sh[NT * NHID];
// fp16 weights
__device__ __half h_qw[NHID * NHID];
__device__ __half h_kw[NHID * NHID];
__device__ __half h_vw[NHID * NHID];
__device__ __half h_ow[NHID * NHID];
__device__ __half h_eg[NEXP * NMI * NHID];
__device__ __half h_eu[NEXP * NMI * NHID];
__device__ __half h_ed[NEXP * NHID * NMI];
__device__ __half h_sg[NSI * NHID];
__device__ __half h_su[NSI * NHID];
__device__ __half h_sd[NHID * NSI];
// fp16 activations
__device__ __half h_xn[NT * NHID];
__device__ __half h_q0[NT * NHID];    // QKV GEMM outputs, (t, head*128+d)
__device__ __half h_k0[NT * NHID];
__device__ __half h_v0[NT * NHID];
__device__ __half h_qr[NT * NHID];    // rope'd + scaled, same layout
__device__ __half h_kr[NT * NHID];
__device__ __half h_ctx[NT * NHID];   // flash output, (t, head*128+d)
__device__ __half h_xg[NSLOT * NHID];
__device__ __half h_gb[NSLOT * NMI];
__device__ __half h_gs[NT * NSI];
// routing state
__device__ int   d_cnt[NEXP];
__device__ int   d_off[NEXP];
__device__ int   d_e0[NT], d_e1[NT], d_r0[NT], d_r1[NT], d_s0[NT], d_s1[NT];
__device__ float d_w0[NT], d_w1[NT];

// ---------------------------------------------------------------------------
// helpers
// ---------------------------------------------------------------------------
__device__ __forceinline__ unsigned smem_u32(const void* p) {
    return (unsigned)__cvta_generic_to_shared(p);
}

__device__ __forceinline__ void cp16(unsigned dst, const void* src, bool pred) {
    int sz = pred ? 16 : 0;
    asm volatile("cp.async.cg.shared.global [%0], [%1], 16, %2;\n"
                 :: "r"(dst), "l"(src), "r"(sz));
}

__device__ __forceinline__ void ldsm4(unsigned& r0, unsigned& r1,
                                      unsigned& r2, unsigned& r3, unsigned addr)
{
    asm volatile("ldmatrix.sync.aligned.m8n8.x4.shared.b16 {%0,%1,%2,%3}, [%4];"
                 : "=r"(r0), "=r"(r1), "=r"(r2), "=r"(r3) : "r"(addr));
}

__device__ __forceinline__ void ldsm4t(unsigned& r0, unsigned& r1,
                                       unsigned& r2, unsigned& r3, unsigned addr)
{
    asm volatile("ldmatrix.sync.aligned.m8n8.x4.trans.shared.b16 {%0,%1,%2,%3}, [%4];"
                 : "=r"(r0), "=r"(r1), "=r"(r2), "=r"(r3) : "r"(addr));
}

__device__ __forceinline__ void mma_f16(float c[4],
    unsigned a0, unsigned a1, unsigned a2, unsigned a3,
    unsigned b0, unsigned b1)
{
    asm volatile(
        "mma.sync.aligned.m16n8k16.row.col.f32.f16.f16.f32 "
        "{%0,%1,%2,%3}, {%4,%5,%6,%7}, {%8,%9}, {%0,%1,%2,%3};\n"
        : "+f"(c[0]), "+f"(c[1]), "+f"(c[2]), "+f"(c[3])
        : "r"(a0), "r"(a1), "r"(a2), "r"(a3), "r"(b0), "r"(b1));
}

__device__ __forceinline__ unsigned packh2(float a, float b) {
    __half2 h = __floats2half2_rn(a, b);
    return *reinterpret_cast<unsigned*>(&h);
}

// ---------------------------------------------------------------------------
// FP16 tensor-core GEMM:  C[M,N] = A[M,K] * B^T  (B stored (N,K) row-major,
// offsets in HALVES).  128x128 block, 8 warps of 64x32 (4x4 m16n8k16),
// 4-stage cp.async, ldmatrix operand loads.  OutT = float or __half.
// ---------------------------------------------------------------------------
template <typename OutT>
__device__ __forceinline__ void hgemm_body(
    const __half* __restrict__ A, const __half* __restrict__ Bm,
    OutT* __restrict__ C, const float* __restrict__ resid,
    int M, int K, int lda, int ldb, int ldc)
{
    extern __shared__ unsigned smu[];
    unsigned* Asm = smu;                         // [STAGES][BM][PAD32]
    unsigned* Bsm = smu + STAGES * STAGE_WORDS;

    const int tid  = threadIdx.x;
    const int wid  = tid >> 5;
    const int lane = tid & 31;
    const int g    = lane >> 2;
    const int tg   = lane & 3;
    const int wm   = (wid & 1) * 64;
    const int wn   = (wid >> 1) * 32;
    const int row0 = blockIdx.y * BM;
    const int col0 = blockIdx.x * BN;
    if (row0 >= M) return;

    const int rA = (lane & 7) + ((lane >> 3) & 1) * 8;
    const int cA = ((lane >> 4) & 1) * 4;
    const int rB = (lane & 7) + ((lane >> 4) & 1) * 8;
    const int cB = ((lane >> 3) & 1) * 4;

    float c[4][4][4];
#pragma unroll
    for (int mi = 0; mi < 4; ++mi)
#pragma unroll
        for (int ni = 0; ni < 4; ++ni)
#pragma unroll
            for (int r = 0; r < 4; ++r) c[mi][ni][r] = 0.f;

    const int lr = tid >> 1;
    const int lqh = (tid & 1) * 16;
    const int lqw = (tid & 1) * 8;
    const int niter = K / BKH;

#pragma unroll
    for (int st = 0; st < STAGES - 1; ++st) {
        if (st < niter) {
            const int k0 = st * BKH;
            const __half* ga = A + (long)(row0 + lr) * lda + k0 + lqh;
            unsigned da = smem_u32(Asm + st * STAGE_WORDS + lr * PAD32 + lqw);
            bool pa = (row0 + lr) < M;
            cp16(da,      ga,     pa);
            cp16(da + 16, ga + 8, pa);
            const __half* gb = Bm + (long)(col0 + lr) * ldb + k0 + lqh;
            unsigned db = smem_u32(Bsm + st * STAGE_WORDS + lr * PAD32 + lqw);
            cp16(db,      gb,     true);
            cp16(db + 16, gb + 8, true);
        }
        asm volatile("cp.async.commit_group;\n");
    }

    int s = 0;
    for (int it = 0; it < niter; ++it) {
        asm volatile("cp.async.wait_group 2;\n");
        __syncthreads();

        const int pf = it + STAGES - 1;
        if (pf < niter) {
            int sl = s + STAGES - 1; if (sl >= STAGES) sl -= STAGES;
            const int k0 = pf * BKH;
            const __half* ga = A + (long)(row0 + lr) * lda + k0 + lqh;
            unsigned da = smem_u32(Asm + sl * STAGE_WORDS + lr * PAD32 + lqw);
            bool pa = (row0 + lr) < M;
            cp16(da,      ga,     pa);
            cp16(da + 16, ga + 8, pa);
            const __half* gb = Bm + (long)(col0 + lr) * ldb + k0 + lqh;
            unsigned db = smem_u32(Bsm + sl * STAGE_WORDS + lr * PAD32 + lqw);
            cp16(db,      gb,     true);
            cp16(db + 16, gb + 8, true);
        }
        asm volatile("cp.async.commit_group;\n");

        const unsigned a_base = smem_u32(Asm + s * STAGE_WORDS);
        const unsigned b_base = smem_u32(Bsm + s * STAGE_WORDS);
#pragma unroll
        for (int kk = 0; kk < 2; ++kk) {
            const int kb = kk * 8;
            unsigned af[4][4], bf[4][2];
#pragma unroll
            for (int mi = 0; mi < 4; ++mi) {
                unsigned addr = a_base +
                    4u * ((wm + mi * 16 + rA) * PAD32 + kb + cA);
                ldsm4(af[mi][0], af[mi][1], af[mi][2], af[mi][3], addr);
            }
#pragma unroll
            for (int p = 0; p < 2; ++p) {
                unsigned addr = b_base +
                    4u * ((wn + p * 16 + rB) * PAD32 + kb + cB);
                ldsm4(bf[2 * p][0], bf[2 * p][1],
                      bf[2 * p + 1][0], bf[2 * p + 1][1], addr);
            }
#pragma unroll
            for (int mi = 0; mi < 4; ++mi)
#pragma unroll
                for (int ni = 0; ni < 4; ++ni)
                    mma_f16(c[mi][ni], af[mi][0], af[mi][1], af[mi][2], af[mi][3],
                            bf[ni][0], bf[ni][1]);
        }
        if (++s >= STAGES) s = 0;
    }

    // ---- epilogue ----
#pragma unroll
    for (int mi = 0; mi < 4; ++mi) {
#pragma unroll
        for (int half = 0; half < 2; ++half) {
            int r = row0 + wm + mi * 16 + g + half * 8;
            if (r < M) {
#pragma unroll
                for (int ni = 0; ni < 4; ++ni) {
                    long off = (long)r * ldc + col0 + wn + ni * 8 + tg * 2;
                    float vx = c[mi][ni][half * 2 + 0];
                    float vy = c[mi][ni][half * 2 + 1];
                    if (resid) {
                        float2 rr = *(const float2*)(resid + off);
                        vx += rr.x; vy += rr.y;
                    }
                    if constexpr (sizeof(OutT) == 4) {
                        float2 v; v.x = vx; v.y = vy;
                        *(float2*)((float*)C + off) = v;
                    } else {
                        __half2 hv = __floats2half2_rn(vx, vy);
                        *(__half2*)((__half*)C + off) = hv;
                    }
                }
            }
        }
    }
}

// ---- generic batched float-out (O-proj, shared-down)
__global__ __launch_bounds__(256, 2)
void hgemm_bat(
    const __half* __restrict__ A, const __half* __restrict__ Bm,
    float* __restrict__ C, const float* __restrict__ resid,
    int M, int K, int lda, int ldb, int ldc,
    long sA, long sB, long sC)
{
    int z = blockIdx.z;
    hgemm_body<float>(A + (long)z * sA, Bm + (long)z * sB, C + (long)z * sC,
                      resid, M, K, lda, ldb, ldc);
}

// ---- fused Q/K/V projection (half out)
__global__ __launch_bounds__(256, 2)
void hqkv_k(const __half* __restrict__ xn)
{
    int z = blockIdx.z;
    const __half* B = (z == 0) ? h_qw : (z == 1) ? h_kw : h_vw;
    __half* C       = (z == 0) ? h_q0 : (z == 1) ? h_k0 : h_v0;
    hgemm_body<__half>(xn, B, C, nullptr, NT, NHID, NHID, NHID, NHID);
}

// ---- fused shared-MLP gate+up
__global__ __launch_bounds__(256, 2)
void hshup_k(const __half* __restrict__ xn,
             float* __restrict__ gs, float* __restrict__ us)
{
    int z = blockIdx.z;
    hgemm_body<float>(xn, z ? h_su : h_sg, z ? us : gs, nullptr,
                      NT, NHID, NHID, NHID, NSI);
}

// ---- fused MoE gate+up grouped: z = 2*e + which
__global__ __launch_bounds__(256, 2)
void hmoeup_k(const __half* __restrict__ xg,
              float* __restrict__ gb, float* __restrict__ ub)
{
    int z = blockIdx.z;
    int e = z >> 1;
    int M = d_cnt[e];
    int off = d_off[e];
    const __half* B = (z & 1) ? h_eu : h_eg;
    float* C        = (z & 1) ? ub : gb;
    hgemm_body<float>(xg + (long)off * NHID, B + (long)e * NMI * NHID,
                      C + (long)off * NMI, nullptr, M, NHID, NHID, NHID, NMI);
}

// ---- MoE down grouped
__global__ __launch_bounds__(256, 2)
void hmoedn_k(const __half* __restrict__ gb, float* __restrict__ yb)
{
    int e = blockIdx.z;
    int M = d_cnt[e];
    int off = d_off[e];
    hgemm_body<float>(gb + (long)off * NMI, h_ed + (long)e * NHID * NMI,
                      yb + (long)off * NHID, nullptr, M, NMI, NMI, NMI, NHID);
}

// ---------------------------------------------------------------------------
// Flash attention: one CTA per (q-tile of 128, head). 8 warps x 16 q-rows.
// K,V tiles 128x128 half, double-buffered cp.async. Online softmax in fp32.
// Q pre-scaled by 1/sqrt(128) in rope. Output half (t, head*128+d).
// ---------------------------------------------------------------------------
__global__ __launch_bounds__(256, 1)
void flash_k(const __half* __restrict__ q, const __half* __restrict__ k,
             const __half* __restrict__ v, __half* __restrict__ o)
{
    extern __shared__ unsigned fsm[];
    unsigned* Qs = fsm;                 // 1 tile
    unsigned* Ks = fsm + FTILE_W;       // 2 stages
    unsigned* Vs = fsm + 3 * FTILE_W;   // 2 stages

    const int qi  = blockIdx.x;         // q tile (0..7)
    const int bh  = blockIdx.y;         // 0..15
    const int b   = bh >> 3, n = bh & 7;
    const int tid = threadIdx.x, wid = tid >> 5, lane = tid & 31;
    const int g   = lane >> 2, tg = lane & 3;
    const int wq  = wid * 16;           // warp q-row base within tile
    const int row0 = qi * 128;

    const long qbase  = ((long)b * NS + row0) * NHID + n * DHEAD;
    const long kvbase = ((long)b * NS) * NHID + n * DHEAD;

    // ldmatrix address components
    const int rA = (lane & 7) + ((lane >> 3) & 1) * 8;   // A rows (Q)
    const int cA = ((lane >> 4) & 1) * 4;
    const int rB = (lane & 7) + ((lane >> 4) & 1) * 8;   // B rows (K)
    const int cB = ((lane >> 3) & 1) * 4;
    const int rV = lane & 15;                            // V (trans) rows
    const int cV = (lane >> 4) * 4;

    // ---- load Q tile ----
    {
        int r = tid >> 1, hh = tid & 1;
        const __half* gq = q + qbase + (long)r * NHID + hh * 64;
        unsigned dq = smem_u32(Qs + r * FPW + hh * 32);
#pragma unroll
        for (int c2 = 0; c2 < 8; ++c2) cp16(dq + c2 * 16, gq + c2 * 8, true);
    }
    // ---- load K0, V0 ----
    {
        int r = tid >> 1, hh = tid & 1;
        const __half* gk = k + kvbase + (long)r * NHID + hh * 64;
        const __half* gv = v + kvbase + (long)r * NHID + hh * 64;
        unsigned dk = smem_u32(Ks + r * FPW + hh * 32);
        unsigned dv = smem_u32(Vs + r * FPW + hh * 32);
#pragma unroll
        for (int c2 = 0; c2 < 8; ++c2) {
            cp16(dk + c2 * 16, gk + c2 * 8, true);
            cp16(dv + c2 * 16, gv + c2 * 8, true);
        }
    }
    asm volatile("cp.async.commit_group;\n");
    asm volatile("cp.async.wait_group 0;\n");
    __syncthreads();

    float oacc[16][4];
#pragma unroll
    for (int j = 0; j < 16; ++j)
#pragma unroll
        for (int r = 0; r < 4; ++r) oacc[j][r] = 0.f;
    float m0 = -1e30f, m1 = -1e30f, l0 = 0.f, l1 = 0.f;

    for (int t = 0; t <= qi; ++t) {
        const int cur = t & 1;
        // prefetch next K,V
        if (t + 1 <= qi) {
            int nxt = (t + 1) & 1;
            int r = tid >> 1, hh = tid & 1;
            const __half* gk = k + kvbase + ((long)(t + 1) * 128 + r) * NHID + hh * 64;
            const __half* gv = v + kvbase + ((long)(t + 1) * 128 + r) * NHID + hh * 64;
            unsigned dk = smem_u32(Ks + nxt * FTILE_W + r * FPW + hh * 32);
            unsigned dv = smem_u32(Vs + nxt * FTILE_W + r * FPW + hh * 32);
#pragma unroll
            for (int c2 = 0; c2 < 8; ++c2) {
                cp16(dk + c2 * 16, gk + c2 * 8, true);
                cp16(dv + c2 * 16, gv + c2 * 8, true);
            }
        }
        asm volatile("cp.async.commit_group;\n");

        const unsigned kbase = smem_u32(Ks + cur * FTILE_W);
        const unsigned vbase = smem_u32(Vs + cur * FTILE_W);
        const unsigned qbse  = smem_u32(Qs);

        // ---- S = Q K^T (16 x 128 per warp) ----
        float sacc[16][4];
#pragma unroll
        for (int j = 0; j < 16; ++j)
#pragma unroll
            for (int r = 0; r < 4; ++r) sacc[j][r] = 0.f;

#pragma unroll
        for (int ks = 0; ks < 8; ++ks) {
            unsigned qa[4];
            ldsm4(qa[0], qa[1], qa[2], qa[3],
                  qbse + 4u * ((wq + rA) * FPW + ks * 8 + cA));
#pragma unroll
            for (int p = 0; p < 8; ++p) {
                unsigned b0, b1, b2, b3;
                ldsm4(b0, b1, b2, b3,
                      kbase + 4u * ((p * 16 + rB) * FPW + ks * 8 + cB));
                mma_f16(sacc[2 * p],     qa[0], qa[1], qa[2], qa[3], b0, b1);
                mma_f16(sacc[2 * p + 1], qa[0], qa[1], qa[2], qa[3], b2, b3);
            }
        }

        // ---- causal mask (diagonal tile only) ----
        if (t == qi) {
            int r0l = wq + g, r1l = wq + g + 8;
#pragma unroll
            for (int j = 0; j < 16; ++j) {
                int col = 8 * j + 2 * tg;
                if (col     > r0l) sacc[j][0] = -1e30f;
                if (col + 1 > r0l) sacc[j][1] = -1e30f;
                if (col     > r1l) sacc[j][2] = -1e30f;
                if (col + 1 > r1l) sacc[j][3] = -1e30f;
            }
        }

        // ---- online softmax ----
        float tm0 = -1e30f, tm1 = -1e30f;
#pragma unroll
        for (int j = 0; j < 16; ++j) {
            tm0 = fmaxf(tm0, fmaxf(sacc[j][0], sacc[j][1]));
            tm1 = fmaxf(tm1, fmaxf(sacc[j][2], sacc[j][3]));
        }
        tm0 = fmaxf(tm0, __shfl_xor_sync(0xffffffffu, tm0, 1));
        tm0 = fmaxf(tm0, __shfl_xor_sync(0xffffffffu, tm0, 2));
        tm1 = fmaxf(tm1, __shfl_xor_sync(0xffffffffu, tm1, 1));
        tm1 = fmaxf(tm1, __shfl_xor_sync(0xffffffffu, tm1, 2));
        float nm0 = fmaxf(m0, tm0), nm1 = fmaxf(m1, tm1);
        float al0 = __expf(m0 - nm0), al1 = __expf(m1 - nm1);

        float rs0 = 0.f, rs1 = 0.f;
        unsigned pf[8][4];
#pragma unroll
        for (int j = 0; j < 16; ++j) {
            float p0 = __expf(sacc[j][0] - nm0);
            float p1 = __expf(sacc[j][1] - nm0);
            float p2 = __expf(sacc[j][2] - nm1);
            float p3 = __expf(sacc[j][3] - nm1);
            rs0 += p0 + p1; rs1 += p2 + p3;
            int ks = j >> 1;
            if ((j & 1) == 0) { pf[ks][0] = packh2(p0, p1); pf[ks][1] = packh2(p2, p3); }
            else              { pf[ks][2] = packh2(p0, p1); pf[ks][3] = packh2(p2, p3); }
        }
        rs0 += __shfl_xor_sync(0xffffffffu, rs0, 1);
        rs0 += __shfl_xor_sync(0xffffffffu, rs0, 2);
        rs1 += __shfl_xor_sync(0xffffffffu, rs1, 1);
        rs1 += __shfl_xor_sync(0xffffffffu, rs1, 2);
        m0 = nm0; m1 = nm1;
        l0 = l0 * al0 + rs0;
        l1 = l1 * al1 + rs1;

#pragma unroll
        for (int j = 0; j < 16; ++j) {
            oacc[j][0] *= al0; oacc[j][1] *= al0;
            oacc[j][2] *= al1; oacc[j][3] *= al1;
        }

        // ---- O += P V ----
#pragma unroll
        for (int ks = 0; ks < 8; ++ks) {
#pragma unroll
            for (int p = 0; p < 8; ++p) {
                unsigned v0, v1, v2, v3;
                ldsm4t(v0, v1, v2, v3,
                       vbase + 4u * ((ks * 16 + rV) * FPW + p * 8 + cV));
                mma_f16(oacc[2 * p],     pf[ks][0], pf[ks][1], pf[ks][2], pf[ks][3], v0, v1);
                mma_f16(oacc[2 * p + 1], pf[ks][0], pf[ks][1], pf[ks][2], pf[ks][3], v2, v3);
            }
        }

        asm volatile("cp.async.wait_group 0;\n");
        __syncthreads();
    }

    // ---- finalize & store ----
    float il0 = 1.f / l0, il1 = 1.f / l1;
    long obase0 = ((long)b * NS + row0 + wq + g) * NHID + n * DHEAD;
    long obase1 = obase0 + 8L * NHID;
#pragma unroll
    for (int j = 0; j < 16; ++j) {
        int col = 8 * j + 2 * tg;
        __half2 h0 = __floats2half2_rn(oacc[j][0] * il0, oacc[j][1] * il0);
        __half2 h1 = __floats2half2_rn(oacc[j][2] * il1, oacc[j][3] * il1);
        *(__half2*)(o + obase0 + col) = h0;
        *(__half2*)(o + obase1 + col) = h1;
    }
}

// ---------------------------------------------------------------------------
// fused weight conversion fp32 -> fp16 (one launch, segment ladder, float4s)
// ---------------------------------------------------------------------------
namespace {
constexpr int W1 = NHID * NHID / 4;
constexpr int WE = NEXP * NMI * NHID / 4;
constexpr int WS = NSI * NHID / 4;
constexpr int CONV_TOT = 4 * W1 + 3 * WE + 3 * WS;
}

__global__ void conv_all_k(
    const float* __restrict__ qw, const float* __restrict__ kw,
    const float* __restrict__ vw, const float* __restrict__ ow,
    const float* __restrict__ eg, const float* __restrict__ eu,
    const float* __restrict__ ed, const float* __restrict__ sg,
    const float* __restrict__ su, const float* __restrict__ sd)
{
    int i = blockIdx.x * 256 + threadIdx.x;
    if (i >= CONV_TOT) return;
    const float* src; __half* dst; int j = i;
    if      (j < 1 * W1) { src = qw; dst = h_qw; }
    else if (j < 2 * W1) { src = kw; dst = h_kw; j -= 1 * W1; }
    else if (j < 3 * W1) { src = vw; dst = h_vw; j -= 2 * W1; }
    else if (j < 4 * W1) { src = ow; dst = h_ow; j -= 3 * W1; }
    else {
        j -= 4 * W1;
        if      (j < 1 * WE) { src = eg; dst = h_eg; }
        else if (j < 2 * WE) { src = eu; dst = h_eu; j -= 1 * WE; }
        else if (j < 3 * WE) { src = ed; dst = h_ed; j -= 2 * WE; }
        else {
            j -= 3 * WE;
            if      (j < 1 * WS) { src = sg; dst = h_sg; }
            else if (j < 2 * WS) { src = su; dst = h_su; j -= 1 * WS; }
            else                 { src = sd; dst = h_sd; j -= 2 * WS; }
        }
    }
    float4 v = *(const float4*)(src + 4 * (long)j);
    __half2 h0 = __floats2half2_rn(v.x, v.y);
    __half2 h1 = __floats2half2_rn(v.z, v.w);
    *(__half2*)(dst + 4 * (long)j)     = h0;
    *(__half2*)(dst + 4 * (long)j + 2) = h1;
}

// ---------------------------------------------------------------------------
// Elementwise / reduction kernels
// ---------------------------------------------------------------------------
__global__ void rmsnorm_k(const float* __restrict__ x,
                          const float* __restrict__ w,
                          __half* __restrict__ oh, float* __restrict__ o32)
{
    int t = blockIdx.x;
    const float* xr = x + (long)t * NHID;
    __shared__ float red[256];
    float s = 0.f;
    for (int i = threadIdx.x; i < NHID; i += 256) { float v = xr[i]; s += v * v; }
    red[threadIdx.x] = s;
    __syncthreads();
    for (int st = 128; st > 0; st >>= 1) {
        if (threadIdx.x < st) red[threadIdx.x] += red[threadIdx.x + st];
        __syncthreads();
    }
    float scale = rsqrtf(red[0] / (float)NHID + 1e-6f);
    for (int i = threadIdx.x; i < NHID; i += 256) {
        float v = xr[i] * scale * w[i];
        oh[(long)t * NHID + i] = __float2half_rn(v);
        if (o32) o32[(long)t * NHID + i] = v;
    }
}

// RoPE on q,k (half->half, coalesced); q also scaled by 1/sqrt(128)
__global__ void rope_k(const __half* __restrict__ q0, const __half* __restrict__ k0,
                       const float* __restrict__ cosp, const float* __restrict__ sinp,
                       __half* __restrict__ qr, __half* __restrict__ kr)
{
    int t = blockIdx.x;
    int s = t % NS;
    const float inv = 0.08838834764831845f;  // 1/sqrt(128)
    for (int i = threadIdx.x; i < NHEAD * 64; i += 256) {
        int n = i >> 6, d = i & 63;
        long base = (long)t * NHID + n * DHEAD;
        float c  = cosp[s * DHEAD + d];
        float sn = sinp[s * DHEAD + d];
        float a0 = __half2float(q0[base + d]);
        float a1 = __half2float(q0[base + d + 64]);
        qr[base + d]      = __float2half_rn((a0 * c - a1 * sn) * inv);
        qr[base + d + 64] = __float2half_rn((a1 * c + a0 * sn) * inv);
        float b0 = __half2float(k0[base + d]);
        float b1 = __half2float(k0[base + d + 64]);
        kr[base + d]      = __float2half_rn(b0 * c - b1 * sn);
        kr[base + d + 64] = __float2half_rn(b1 * c + b0 * sn);
    }
}

__global__ void zero_cnt_k() { if (threadIdx.x < NEXP) d_cnt[threadIdx.x] = 0; }

__global__ void gate_k(const float* __restrict__ xn, const float* __restrict__ gw)
{
    int t = blockIdx.x;
    int tid = threadIdx.x, w = tid >> 5, lane = tid & 31;
    const float* xr = xn + (long)t * NHID;
    const float* gr = gw + (long)w * NHID;
    float s = 0.f;
    for (int i = lane; i < NHID; i += 32) s += xr[i] * gr[i];
    for (int o = 16; o; o >>= 1) s += __shfl_xor_sync(0xffffffffu, s, o);
    __shared__ float lg[NEXP];
    if (lane == 0) lg[w] = s;
    __syncthreads();
    if (tid == 0) {
        float mx = lg[0];
        for (int e = 1; e < NEXP; ++e) mx = fmaxf(mx, lg[e]);
        float p[NEXP];
        for (int e = 0; e < NEXP; ++e) p[e] = expf(lg[e] - mx);
        int e0 = 0; float b0 = p[0];
        for (int e = 1; e < NEXP; ++e) if (p[e] > b0) { b0 = p[e]; e0 = e; }
        int e1 = -1; float b1 = -1.f;
        for (int e = 0; e < NEXP; ++e)
            if (e != e0 && p[e] > b1) { b1 = p[e]; e1 = e; }
        float denom = b0 + b1;
        d_e0[t] = e0; d_e1[t] = e1;
        d_w0[t] = b0 / denom; d_w1[t] = b1 / denom;
        d_r0[t] = atomicAdd(&d_cnt[e0], 1);
        d_r1[t] = atomicAdd(&d_cnt[e1], 1);
    }
}

__global__ void scan_k()
{
    if (threadIdx.x == 0) {
        int a = 0;
        for (int e = 0; e < NEXP; ++e) { d_off[e] = a; a += d_cnt[e]; }
    }
}

__global__ void gather_k(const __half* __restrict__ xnh)
{
    int t = blockIdx.x;
    __shared__ int ss[2];
    if (threadIdx.x == 0) {
        int s0 = d_off[d_e0[t]] + d_r0[t];
        int s1 = d_off[d_e1[t]] + d_r1[t];
        d_s0[t] = s0; d_s1[t] = s1;
        ss[0] = s0; ss[1] = s1;
    }
    __syncthreads();
    const uint4* src = (const uint4*)(xnh + (long)t * NHID);
    uint4* dst0 = (uint4*)(h_xg + (long)ss[0] * NHID);
    uint4* dst1 = (uint4*)(h_xg + (long)ss[1] * NHID);
    for (int i = threadIdx.x; i < NHID / 8; i += 256) {
        uint4 v = src[i];
        dst0[i] = v;
        dst1[i] = v;
    }
}

__global__ void silumul_k(const float* __restrict__ g, const float* __restrict__ u,
                          __half* __restrict__ o, long n)
{
    long i = (long)blockIdx.x * 256 + threadIdx.x;
    if (i < n) {
        float gv = g[i];
        float s = 1.f / (1.f + expf(-gv));
        o[i] = __float2half_rn(gv * s * u[i]);
    }
}

__global__ void combine_k(const float* __restrict__ x1,
                          const float* __restrict__ sh,
                          float* __restrict__ out)
{
    int t = blockIdx.x;
    float w0 = d_w0[t], w1 = d_w1[t];
    long o0 = (long)d_s0[t] * NHID;
    long o1 = (long)d_s1[t] * NHID;
    for (int i = threadIdx.x; i < NHID; i += 256) {
        long idx = (long)t * NHID + i;
        out[idx] = x1[idx] + sh[idx] + w0 * d_ybuf[o0 + i] + w1 * d_ybuf[o1 + i];
    }
}

// ---------------------------------------------------------------------------
// Launch
// ---------------------------------------------------------------------------
extern "C" void kernel_launch(void* const* d_in, const int* in_sizes, int n_in,
                              void* d_out, int out_size)
{
    (void)in_sizes; (void)n_in; (void)out_size;

    const float* hs   = (const float*)d_in[0];
    const float* ln1  = (const float*)d_in[1];
    const float* ln2  = (const float*)d_in[2];
    const float* q_w  = (const float*)d_in[3];
    const float* k_w  = (const float*)d_in[4];
    const float* v_w  = (const float*)d_in[5];
    const float* o_w  = (const float*)d_in[6];
    const float* cosp = (const float*)d_in[7];
    const float* sinp = (const float*)d_in[8];
    const float* gate = (const float*)d_in[9];
    const float* eg   = (const float*)d_in[10];
    const float* eu   = (const float*)d_in[11];
    const float* ed   = (const float*)d_in[12];
    const float* sg   = (const float*)d_in[13];
    const float* su   = (const float*)d_in[14];
    const float* sd   = (const float*)d_in[15];
    float* out = (float*)d_out;

    float *xn32, *x1, *gb, *ub, *yb, *gs, *us, *sh;
    __half *hxn, *hq0, *hk0, *hv0, *hqr, *hkr, *hctx, *hxg, *hgb, *hgs;
    __half *how2, *hsd2;
    cudaGetSymbolAddress((void**)&xn32, d_xn32);
    cudaGetSymbolAddress((void**)&x1,  d_x1);
    cudaGetSymbolAddress((void**)&gb,  d_gbuf);
    cudaGetSymbolAddress((void**)&ub,  d_ubuf);
    cudaGetSymbolAddress((void**)&yb,  d_ybuf);
    cudaGetSymbolAddress((void**)&gs,  d_gs);
    cudaGetSymbolAddress((void**)&us,  d_us);
    cudaGetSymbolAddress((void**)&sh,  d_sh);
    cudaGetSymbolAddress((void**)&hxn, h_xn);
    cudaGetSymbolAddress((void**)&hq0, h_q0);
    cudaGetSymbolAddress((void**)&hk0, h_k0);
    cudaGetSymbolAddress((void**)&hv0, h_v0);
    cudaGetSymbolAddress((void**)&hqr, h_qr);
    cudaGetSymbolAddress((void**)&hkr, h_kr);
    cudaGetSymbolAddress((void**)&hctx, h_ctx);
    cudaGetSymbolAddress((void**)&hxg, h_xg);
    cudaGetSymbolAddress((void**)&hgb, h_gb);
    cudaGetSymbolAddress((void**)&hgs, h_gs);
    cudaGetSymbolAddress((void**)&how2, h_ow);
    cudaGetSymbolAddress((void**)&hsd2, h_sd);

    cudaFuncSetAttribute(hgemm_bat,
        cudaFuncAttributeMaxDynamicSharedMemorySize, SMEM_BYTES);
    cudaFuncSetAttribute(hqkv_k,
        cudaFuncAttributeMaxDynamicSharedMemorySize, SMEM_BYTES);
    cudaFuncSetAttribute(hshup_k,
        cudaFuncAttributeMaxDynamicSharedMemorySize, SMEM_BYTES);
    cudaFuncSetAttribute(hmoeup_k,
        cudaFuncAttributeMaxDynamicSharedMemorySize, SMEM_BYTES);
    cudaFuncSetAttribute(hmoedn_k,
        cudaFuncAttributeMaxDynamicSharedMemorySize, SMEM_BYTES);
    cudaFuncSetAttribute(flash_k,
        cudaFuncAttributeMaxDynamicSharedMemorySize, FLASH_SMEM);

    // ---- all weight conversions in one launch ----
    conv_all_k<<<(CONV_TOT + 255) / 256, 256>>>(q_w, k_w, v_w, o_w,
                                                eg, eu, ed, sg, su, sd);

    const dim3 gQKV(NHID / BN, NT / BM, 3);
    const dim3 gFlash(NS / 128, NB * NHEAD);
    const dim3 gProj(NHID / BN, NT / BM);
    const dim3 gShUp(NSI / BN, NT / BM, 2);
    const dim3 gMoeUp(NMI / BN, NSLOT / BM, 2 * NEXP);
    const dim3 gMoeDn(NHID / BN, NSLOT / BM, NEXP);

    // ---- attention ----
    rmsnorm_k<<<NT, 256>>>(hs, ln1, hxn, nullptr);
    hqkv_k<<<gQKV, 256, SMEM_BYTES>>>(hxn);
    rope_k<<<NT, 256>>>(hq0, hk0, cosp, sinp, hqr, hkr);
    flash_k<<<gFlash, 256, FLASH_SMEM>>>(hqr, hkr, hv0, hctx);
    hgemm_bat<<<gProj, 256, SMEM_BYTES>>>(hctx, how2, x1, hs,
        NT, NHID, NHID, NHID, NHID, 0, 0, 0);

    // ---- MoE ----
    rmsnorm_k<<<NT, 256>>>(x1, ln2, hxn, xn32);
    zero_cnt_k<<<1, 32>>>();
    gate_k<<<NT, 256>>>(xn32, gate);
    scan_k<<<1, 1>>>();
    gather_k<<<NT, 256>>>(hxn);

    hmoeup_k<<<gMoeUp, 256, SMEM_BYTES>>>(hxg, gb, ub);
    silumul_k<<<(unsigned)(((long)NSLOT * NMI + 255) / 256), 256>>>(
        gb, ub, hgb, (long)NSLOT * NMI);
    hmoedn_k<<<gMoeDn, 256, SMEM_BYTES>>>(hgb, yb);

    // ---- shared MLP ----
    hshup_k<<<gShUp, 256, SMEM_BYTES>>>(hxn, gs, us);
    silumul_k<<<(unsigned)(((long)NT * NSI + 255) / 256), 256>>>(
        gs, us, hgs, (long)NT * NSI);
    hgemm_bat<<<gProj, 256, SMEM_BYTES>>>(hgs, hsd2, sh, nullptr,
        NT, NSI, NSI, NSI, NHID, 0, 0, 0);

    // ---- combine ----
    combine_k<<<NT, 256>>>(x1, sh, out);
}

// round 11
// speedup vs baseline: 1.8484x; 1.0316x over previous
#include <cuda_runtime.h>
#include <cuda_fp16.h>
#include <math.h>

// ---------------------------------------------------------------------------
// Problem constants
// ---------------------------------------------------------------------------
namespace {
constexpr int NB = 2, NS = 1024, NHID = 1024, NHEAD = 8, DHEAD = 128;
constexpr int NEXP = 8, NMI = 1024, NSI = 2048;
constexpr int NT = NB * NS;          // 2048 tokens
constexpr int NSLOT = 2 * NT;        // 4096 expert slots (top-2)

// fp16 GEMM tile: 128x128x32(halves), 8 warps of 64x32, 4-stage cp.async
constexpr int BM = 128, BN = 128, BKH = 32;
constexpr int PAD32 = 20;                        // row stride in b32 (80B)
constexpr int STAGES = 4;
constexpr int STAGE_WORDS = BM * PAD32;          // 2560 b32 per tile-stage
constexpr int SMEM_BYTES = 2 * STAGES * STAGE_WORDS * 4;   // 81920

// flash attention smem: Q + 2xK + 2xV tiles of 128 rows x 68 words
constexpr int FPW = 68;                          // words per row (136 halves)
constexpr int FTILE_W = 128 * FPW;               // 8704 words per tile
constexpr int FLASH_SMEM = 5 * FTILE_W * 4;      // 174080 bytes
}

// ---------------------------------------------------------------------------
// Static device scratch (no allocations allowed)
// ---------------------------------------------------------------------------
// fp32 buffers
__device__ float d_xn32[NT * NHID];
__device__ float d_x1[NT * NHID];
__device__ float d_sh[NT * NHID];
// fp16 weights
__device__ __half h_qw[NHID * NHID];
__device__ __half h_kw[NHID * NHID];
__device__ __half h_vw[NHID * NHID];
__device__ __half h_ow[NHID * NHID];
__device__ __half h_eg[NEXP * NMI * NHID];
__device__ __half h_eu[NEXP * NMI * NHID];
__device__ __half h_ed[NEXP * NHID * NMI];
__device__ __half h_sg[NSI * NHID];
__device__ __half h_su[NSI * NHID];
__device__ __half h_sd[NHID * NSI];
// fp16 activations
__device__ __half h_xn[NT * NHID];
__device__ __half h_q0[NT * NHID];    // QKV GEMM outputs, (t, head*128+d)
__device__ __half h_k0[NT * NHID];
__device__ __half h_v0[NT * NHID];
__device__ __half h_qr[NT * NHID];    // rope'd + scaled
__device__ __half h_kr[NT * NHID];
__device__ __half h_ctx[NT * NHID];   // flash output
__device__ __half h_xg[NSLOT * NHID];
__device__ __half h_gbuf[NSLOT * NMI];   // MoE gate GEMM out (half)
__device__ __half h_ubuf[NSLOT * NMI];   // MoE up GEMM out (half)
__device__ __half h_gb[NSLOT * NMI];     // silu(g)*u (half)
__device__ __half h_ybuf[NSLOT * NHID];  // MoE down out (half)
__device__ __half h_gs32[NT * NSI];      // shared gate GEMM out (half)
__device__ __half h_us32[NT * NSI];      // shared up GEMM out (half)
__device__ __half h_gs[NT * NSI];        // silu(g)*u (half)
// routing state
__device__ int   d_cnt[NEXP];
__device__ int   d_off[NEXP];
__device__ int   d_e0[NT], d_e1[NT], d_r0[NT], d_r1[NT], d_s0[NT], d_s1[NT];
__device__ float d_w0[NT], d_w1[NT];

// ---------------------------------------------------------------------------
// helpers
// ---------------------------------------------------------------------------
__device__ __forceinline__ unsigned smem_u32(const void* p) {
    return (unsigned)__cvta_generic_to_shared(p);
}

__device__ __forceinline__ void cp16(unsigned dst, const void* src, bool pred) {
    int sz = pred ? 16 : 0;
    asm volatile("cp.async.cg.shared.global [%0], [%1], 16, %2;\n"
                 :: "r"(dst), "l"(src), "r"(sz));
}

__device__ __forceinline__ void ldsm4(unsigned& r0, unsigned& r1,
                                      unsigned& r2, unsigned& r3, unsigned addr)
{
    asm volatile("ldmatrix.sync.aligned.m8n8.x4.shared.b16 {%0,%1,%2,%3}, [%4];"
                 : "=r"(r0), "=r"(r1), "=r"(r2), "=r"(r3) : "r"(addr));
}

__device__ __forceinline__ void ldsm4t(unsigned& r0, unsigned& r1,
                                       unsigned& r2, unsigned& r3, unsigned addr)
{
    asm volatile("ldmatrix.sync.aligned.m8n8.x4.trans.shared.b16 {%0,%1,%2,%3}, [%4];"
                 : "=r"(r0), "=r"(r1), "=r"(r2), "=r"(r3) : "r"(addr));
}

__device__ __forceinline__ void mma_f16(float c[4],
    unsigned a0, unsigned a1, unsigned a2, unsigned a3,
    unsigned b0, unsigned b1)
{
    asm volatile(
        "mma.sync.aligned.m16n8k16.row.col.f32.f16.f16.f32 "
        "{%0,%1,%2,%3}, {%4,%5,%6,%7}, {%8,%9}, {%0,%1,%2,%3};\n"
        : "+f"(c[0]), "+f"(c[1]), "+f"(c[2]), "+f"(c[3])
        : "r"(a0), "r"(a1), "r"(a2), "r"(a3), "r"(b0), "r"(b1));
}

__device__ __forceinline__ unsigned packh2(float a, float b) {
    __half2 h = __floats2half2_rn(a, b);
    return *reinterpret_cast<unsigned*>(&h);
}

// ---------------------------------------------------------------------------
// FP16 tensor-core GEMM:  C[M,N] = A[M,K] * B^T  (B stored (N,K) row-major,
// offsets in HALVES).  128x128 block, 8 warps of 64x32 (4x4 m16n8k16),
// 4-stage cp.async, ldmatrix operand loads.  OutT = float or __half.
// ---------------------------------------------------------------------------
template <typename OutT>
__device__ __forceinline__ void hgemm_body(
    const __half* __restrict__ A, const __half* __restrict__ Bm,
    OutT* __restrict__ C, const float* __restrict__ resid,
    int M, int K, int lda, int ldb, int ldc)
{
    extern __shared__ unsigned smu[];
    unsigned* Asm = smu;                         // [STAGES][BM][PAD32]
    unsigned* Bsm = smu + STAGES * STAGE_WORDS;

    const int tid  = threadIdx.x;
    const int wid  = tid >> 5;
    const int lane = tid & 31;
    const int g    = lane >> 2;
    const int tg   = lane & 3;
    const int wm   = (wid & 1) * 64;
    const int wn   = (wid >> 1) * 32;
    const int row0 = blockIdx.y * BM;
    const int col0 = blockIdx.x * BN;
    if (row0 >= M) return;

    const int rA = (lane & 7) + ((lane >> 3) & 1) * 8;
    const int cA = ((lane >> 4) & 1) * 4;
    const int rB = (lane & 7) + ((lane >> 4) & 1) * 8;
    const int cB = ((lane >> 3) & 1) * 4;

    float c[4][4][4];
#pragma unroll
    for (int mi = 0; mi < 4; ++mi)
#pragma unroll
        for (int ni = 0; ni < 4; ++ni)
#pragma unroll
            for (int r = 0; r < 4; ++r) c[mi][ni][r] = 0.f;

    const int lr = tid >> 1;
    const int lqh = (tid & 1) * 16;
    const int lqw = (tid & 1) * 8;
    const int niter = K / BKH;

#pragma unroll
    for (int st = 0; st < STAGES - 1; ++st) {
        if (st < niter) {
            const int k0 = st * BKH;
            const __half* ga = A + (long)(row0 + lr) * lda + k0 + lqh;
            unsigned da = smem_u32(Asm + st * STAGE_WORDS + lr * PAD32 + lqw);
            bool pa = (row0 + lr) < M;
            cp16(da,      ga,     pa);
            cp16(da + 16, ga + 8, pa);
            const __half* gb = Bm + (long)(col0 + lr) * ldb + k0 + lqh;
            unsigned db = smem_u32(Bsm + st * STAGE_WORDS + lr * PAD32 + lqw);
            cp16(db,      gb,     true);
            cp16(db + 16, gb + 8, true);
        }
        asm volatile("cp.async.commit_group;\n");
    }

    int s = 0;
    for (int it = 0; it < niter; ++it) {
        asm volatile("cp.async.wait_group 2;\n");
        __syncthreads();

        const int pf = it + STAGES - 1;
        if (pf < niter) {
            int sl = s + STAGES - 1; if (sl >= STAGES) sl -= STAGES;
            const int k0 = pf * BKH;
            const __half* ga = A + (long)(row0 + lr) * lda + k0 + lqh;
            unsigned da = smem_u32(Asm + sl * STAGE_WORDS + lr * PAD32 + lqw);
            bool pa = (row0 + lr) < M;
            cp16(da,      ga,     pa);
            cp16(da + 16, ga + 8, pa);
            const __half* gb = Bm + (long)(col0 + lr) * ldb + k0 + lqh;
            unsigned db = smem_u32(Bsm + sl * STAGE_WORDS + lr * PAD32 + lqw);
            cp16(db,      gb,     true);
            cp16(db + 16, gb + 8, true);
        }
        asm volatile("cp.async.commit_group;\n");

        const unsigned a_base = smem_u32(Asm + s * STAGE_WORDS);
        const unsigned b_base = smem_u32(Bsm + s * STAGE_WORDS);
#pragma unroll
        for (int kk = 0; kk < 2; ++kk) {
            const int kb = kk * 8;
            unsigned af[4][4], bf[4][2];
#pragma unroll
            for (int mi = 0; mi < 4; ++mi) {
                unsigned addr = a_base +
                    4u * ((wm + mi * 16 + rA) * PAD32 + kb + cA);
                ldsm4(af[mi][0], af[mi][1], af[mi][2], af[mi][3], addr);
            }
#pragma unroll
            for (int p = 0; p < 2; ++p) {
                unsigned addr = b_base +
                    4u * ((wn + p * 16 + rB) * PAD32 + kb + cB);
                ldsm4(bf[2 * p][0], bf[2 * p][1],
                      bf[2 * p + 1][0], bf[2 * p + 1][1], addr);
            }
#pragma unroll
            for (int mi = 0; mi < 4; ++mi)
#pragma unroll
                for (int ni = 0; ni < 4; ++ni)
                    mma_f16(c[mi][ni], af[mi][0], af[mi][1], af[mi][2], af[mi][3],
                            bf[ni][0], bf[ni][1]);
        }
        if (++s >= STAGES) s = 0;
    }

    // ---- epilogue ----
#pragma unroll
    for (int mi = 0; mi < 4; ++mi) {
#pragma unroll
        for (int half = 0; half < 2; ++half) {
            int r = row0 + wm + mi * 16 + g + half * 8;
            if (r < M) {
#pragma unroll
                for (int ni = 0; ni < 4; ++ni) {
                    long off = (long)r * ldc + col0 + wn + ni * 8 + tg * 2;
                    float vx = c[mi][ni][half * 2 + 0];
                    float vy = c[mi][ni][half * 2 + 1];
                    if (resid) {
                        float2 rr = *(const float2*)(resid + off);
                        vx += rr.x; vy += rr.y;
                    }
                    if constexpr (sizeof(OutT) == 4) {
                        float2 v; v.x = vx; v.y = vy;
                        *(float2*)((float*)C + off) = v;
                    } else {
                        __half2 hv = __floats2half2_rn(vx, vy);
                        *(__half2*)((__half*)C + off) = hv;
                    }
                }
            }
        }
    }
}

// ---- generic batched float-out (O-proj, shared-down)
__global__ __launch_bounds__(256, 2)
void hgemm_bat(
    const __half* __restrict__ A, const __half* __restrict__ Bm,
    float* __restrict__ C, const float* __restrict__ resid,
    int M, int K, int lda, int ldb, int ldc,
    long sA, long sB, long sC)
{
    int z = blockIdx.z;
    hgemm_body<float>(A + (long)z * sA, Bm + (long)z * sB, C + (long)z * sC,
                      resid, M, K, lda, ldb, ldc);
}

// ---- fused Q/K/V projection (half out)
__global__ __launch_bounds__(256, 2)
void hqkv_k(const __half* __restrict__ xn)
{
    int z = blockIdx.z;
    const __half* B = (z == 0) ? h_qw : (z == 1) ? h_kw : h_vw;
    __half* C       = (z == 0) ? h_q0 : (z == 1) ? h_k0 : h_v0;
    hgemm_body<__half>(xn, B, C, nullptr, NT, NHID, NHID, NHID, NHID);
}

// ---- fused shared-MLP gate+up (half out)
__global__ __launch_bounds__(256, 2)
void hshup_k(const __half* __restrict__ xn)
{
    int z = blockIdx.z;
    hgemm_body<__half>(xn, z ? h_su : h_sg, z ? h_us32 : h_gs32, nullptr,
                       NT, NHID, NHID, NHID, NSI);
}

// ---- fused MoE gate+up grouped (half out): z = 2*e + which
__global__ __launch_bounds__(256, 2)
void hmoeup_k(const __half* __restrict__ xg)
{
    int z = blockIdx.z;
    int e = z >> 1;
    int M = d_cnt[e];
    int off = d_off[e];
    const __half* B = (z & 1) ? h_eu : h_eg;
    __half* C       = (z & 1) ? h_ubuf : h_gbuf;
    hgemm_body<__half>(xg + (long)off * NHID, B + (long)e * NMI * NHID,
                       C + (long)off * NMI, nullptr, M, NHID, NHID, NHID, NMI);
}

// ---- MoE down grouped (half out)
__global__ __launch_bounds__(256, 2)
void hmoedn_k(const __half* __restrict__ gb)
{
    int e = blockIdx.z;
    int M = d_cnt[e];
    int off = d_off[e];
    hgemm_body<__half>(gb + (long)off * NMI, h_ed + (long)e * NHID * NMI,
                       h_ybuf + (long)off * NHID, nullptr, M, NMI, NMI, NMI, NHID);
}

// ---------------------------------------------------------------------------
// Flash attention (r8, unchanged): one CTA per (q-tile 128, head).
// ---------------------------------------------------------------------------
__global__ __launch_bounds__(256, 1)
void flash_k(const __half* __restrict__ q, const __half* __restrict__ k,
             const __half* __restrict__ v, __half* __restrict__ o)
{
    extern __shared__ unsigned fsm[];
    unsigned* Qs = fsm;
    unsigned* Ks = fsm + FTILE_W;
    unsigned* Vs = fsm + 3 * FTILE_W;

    const int qi  = blockIdx.x;
    const int bh  = blockIdx.y;
    const int b   = bh >> 3, n = bh & 7;
    const int tid = threadIdx.x, wid = tid >> 5, lane = tid & 31;
    const int g   = lane >> 2, tg = lane & 3;
    const int wq  = wid * 16;
    const int row0 = qi * 128;

    const long qbase  = ((long)b * NS + row0) * NHID + n * DHEAD;
    const long kvbase = ((long)b * NS) * NHID + n * DHEAD;

    const int rA = (lane & 7) + ((lane >> 3) & 1) * 8;
    const int cA = ((lane >> 4) & 1) * 4;
    const int rB = (lane & 7) + ((lane >> 4) & 1) * 8;
    const int cB = ((lane >> 3) & 1) * 4;
    const int rV = lane & 15;
    const int cV = (lane >> 4) * 4;

    {
        int r = tid >> 1, hh = tid & 1;
        const __half* gq = q + qbase + (long)r * NHID + hh * 64;
        unsigned dq = smem_u32(Qs + r * FPW + hh * 32);
#pragma unroll
        for (int c2 = 0; c2 < 8; ++c2) cp16(dq + c2 * 16, gq + c2 * 8, true);
    }
    {
        int r = tid >> 1, hh = tid & 1;
        const __half* gk = k + kvbase + (long)r * NHID + hh * 64;
        const __half* gv = v + kvbase + (long)r * NHID + hh * 64;
        unsigned dk = smem_u32(Ks + r * FPW + hh * 32);
        unsigned dv = smem_u32(Vs + r * FPW + hh * 32);
#pragma unroll
        for (int c2 = 0; c2 < 8; ++c2) {
            cp16(dk + c2 * 16, gk + c2 * 8, true);
            cp16(dv + c2 * 16, gv + c2 * 8, true);
        }
    }
    asm volatile("cp.async.commit_group;\n");
    asm volatile("cp.async.wait_group 0;\n");
    __syncthreads();

    float oacc[16][4];
#pragma unroll
    for (int j = 0; j < 16; ++j)
#pragma unroll
        for (int r = 0; r < 4; ++r) oacc[j][r] = 0.f;
    float m0 = -1e30f, m1 = -1e30f, l0 = 0.f, l1 = 0.f;

    for (int t = 0; t <= qi; ++t) {
        const int cur = t & 1;
        if (t + 1 <= qi) {
            int nxt = (t + 1) & 1;
            int r = tid >> 1, hh = tid & 1;
            const __half* gk = k + kvbase + ((long)(t + 1) * 128 + r) * NHID + hh * 64;
            const __half* gv = v + kvbase + ((long)(t + 1) * 128 + r) * NHID + hh * 64;
            unsigned dk = smem_u32(Ks + nxt * FTILE_W + r * FPW + hh * 32);
            unsigned dv = smem_u32(Vs + nxt * FTILE_W + r * FPW + hh * 32);
#pragma unroll
            for (int c2 = 0; c2 < 8; ++c2) {
                cp16(dk + c2 * 16, gk + c2 * 8, true);
                cp16(dv + c2 * 16, gv + c2 * 8, true);
            }
        }
        asm volatile("cp.async.commit_group;\n");

        const unsigned kbase = smem_u32(Ks + cur * FTILE_W);
        const unsigned vbase = smem_u32(Vs + cur * FTILE_W);
        const unsigned qbse  = smem_u32(Qs);

        float sacc[16][4];
#pragma unroll
        for (int j = 0; j < 16; ++j)
#pragma unroll
            for (int r = 0; r < 4; ++r) sacc[j][r] = 0.f;

#pragma unroll
        for (int ks = 0; ks < 8; ++ks) {
            unsigned qa[4];
            ldsm4(qa[0], qa[1], qa[2], qa[3],
                  qbse + 4u * ((wq + rA) * FPW + ks * 8 + cA));
#pragma unroll
            for (int p = 0; p < 8; ++p) {
                unsigned b0, b1, b2, b3;
                ldsm4(b0, b1, b2, b3,
                      kbase + 4u * ((p * 16 + rB) * FPW + ks * 8 + cB));
                mma_f16(sacc[2 * p],     qa[0], qa[1], qa[2], qa[3], b0, b1);
                mma_f16(sacc[2 * p + 1], qa[0], qa[1], qa[2], qa[3], b2, b3);
            }
        }

        if (t == qi) {
            int r0l = wq + g, r1l = wq + g + 8;
#pragma unroll
            for (int j = 0; j < 16; ++j) {
                int col = 8 * j + 2 * tg;
                if (col     > r0l) sacc[j][0] = -1e30f;
                if (col + 1 > r0l) sacc[j][1] = -1e30f;
                if (col     > r1l) sacc[j][2] = -1e30f;
                if (col + 1 > r1l) sacc[j][3] = -1e30f;
            }
        }

        float tm0 = -1e30f, tm1 = -1e30f;
#pragma unroll
        for (int j = 0; j < 16; ++j) {
            tm0 = fmaxf(tm0, fmaxf(sacc[j][0], sacc[j][1]));
            tm1 = fmaxf(tm1, fmaxf(sacc[j][2], sacc[j][3]));
        }
        tm0 = fmaxf(tm0, __shfl_xor_sync(0xffffffffu, tm0, 1));
        tm0 = fmaxf(tm0, __shfl_xor_sync(0xffffffffu, tm0, 2));
        tm1 = fmaxf(tm1, __shfl_xor_sync(0xffffffffu, tm1, 1));
        tm1 = fmaxf(tm1, __shfl_xor_sync(0xffffffffu, tm1, 2));
        float nm0 = fmaxf(m0, tm0), nm1 = fmaxf(m1, tm1);
        float al0 = __expf(m0 - nm0), al1 = __expf(m1 - nm1);

        float rs0 = 0.f, rs1 = 0.f;
        unsigned pf[8][4];
#pragma unroll
        for (int j = 0; j < 16; ++j) {
            float p0 = __expf(sacc[j][0] - nm0);
            float p1 = __expf(sacc[j][1] - nm0);
            float p2 = __expf(sacc[j][2] - nm1);
            float p3 = __expf(sacc[j][3] - nm1);
            rs0 += p0 + p1; rs1 += p2 + p3;
            int ks = j >> 1;
            if ((j & 1) == 0) { pf[ks][0] = packh2(p0, p1); pf[ks][1] = packh2(p2, p3); }
            else              { pf[ks][2] = packh2(p0, p1); pf[ks][3] = packh2(p2, p3); }
        }
        rs0 += __shfl_xor_sync(0xffffffffu, rs0, 1);
        rs0 += __shfl_xor_sync(0xffffffffu, rs0, 2);
        rs1 += __shfl_xor_sync(0xffffffffu, rs1, 1);
        rs1 += __shfl_xor_sync(0xffffffffu, rs1, 2);
        m0 = nm0; m1 = nm1;
        l0 = l0 * al0 + rs0;
        l1 = l1 * al1 + rs1;

#pragma unroll
        for (int j = 0; j < 16; ++j) {
            oacc[j][0] *= al0; oacc[j][1] *= al0;
            oacc[j][2] *= al1; oacc[j][3] *= al1;
        }

#pragma unroll
        for (int ks = 0; ks < 8; ++ks) {
#pragma unroll
            for (int p = 0; p < 8; ++p) {
                unsigned v0, v1, v2, v3;
                ldsm4t(v0, v1, v2, v3,
                       vbase + 4u * ((ks * 16 + rV) * FPW + p * 8 + cV));
                mma_f16(oacc[2 * p],     pf[ks][0], pf[ks][1], pf[ks][2], pf[ks][3], v0, v1);
                mma_f16(oacc[2 * p + 1], pf[ks][0], pf[ks][1], pf[ks][2], pf[ks][3], v2, v3);
            }
        }

        asm volatile("cp.async.wait_group 0;\n");
        __syncthreads();
    }

    float il0 = 1.f / l0, il1 = 1.f / l1;
    long obase0 = ((long)b * NS + row0 + wq + g) * NHID + n * DHEAD;
    long obase1 = obase0 + 8L * NHID;
#pragma unroll
    for (int j = 0; j < 16; ++j) {
        int col = 8 * j + 2 * tg;
        __half2 h0 = __floats2half2_rn(oacc[j][0] * il0, oacc[j][1] * il0);
        __half2 h1 = __floats2half2_rn(oacc[j][2] * il1, oacc[j][3] * il1);
        *(__half2*)(o + obase0 + col) = h0;
        *(__half2*)(o + obase1 + col) = h1;
    }
}

// ---------------------------------------------------------------------------
// fused weight conversion fp32 -> fp16 (one launch, segment ladder, float4s)
// ---------------------------------------------------------------------------
namespace {
constexpr int W1 = NHID * NHID / 4;
constexpr int WE = NEXP * NMI * NHID / 4;
constexpr int WS = NSI * NHID / 4;
constexpr int CONV_TOT = 4 * W1 + 3 * WE + 3 * WS;
}

__global__ void conv_all_k(
    const float* __restrict__ qw, const float* __restrict__ kw,
    const float* __restrict__ vw, const float* __restrict__ ow,
    const float* __restrict__ eg, const float* __restrict__ eu,
    const float* __restrict__ ed, const float* __restrict__ sg,
    const float* __restrict__ su, const float* __restrict__ sd)
{
    int i = blockIdx.x * 256 + threadIdx.x;
    if (i >= CONV_TOT) return;
    const float* src; __half* dst; int j = i;
    if      (j < 1 * W1) { src = qw; dst = h_qw; }
    else if (j < 2 * W1) { src = kw; dst = h_kw; j -= 1 * W1; }
    else if (j < 3 * W1) { src = vw; dst = h_vw; j -= 2 * W1; }
    else if (j < 4 * W1) { src = ow; dst = h_ow; j -= 3 * W1; }
    else {
        j -= 4 * W1;
        if      (j < 1 * WE) { src = eg; dst = h_eg; }
        else if (j < 2 * WE) { src = eu; dst = h_eu; j -= 1 * WE; }
        else if (j < 3 * WE) { src = ed; dst = h_ed; j -= 2 * WE; }
        else {
            j -= 3 * WE;
            if      (j < 1 * WS) { src = sg; dst = h_sg; }
            else if (j < 2 * WS) { src = su; dst = h_su; j -= 1 * WS; }
            else                 { src = sd; dst = h_sd; j -= 2 * WS; }
        }
    }
    float4 v = *(const float4*)(src + 4 * (long)j);
    __half2 h0 = __floats2half2_rn(v.x, v.y);
    __half2 h1 = __floats2half2_rn(v.z, v.w);
    *(__half2*)(dst + 4 * (long)j)     = h0;
    *(__half2*)(dst + 4 * (long)j + 2) = h1;
}

// ---------------------------------------------------------------------------
// Elementwise / reduction kernels
// ---------------------------------------------------------------------------
__global__ void rmsnorm_k(const float* __restrict__ x,
                          const float* __restrict__ w,
                          __half* __restrict__ oh, float* __restrict__ o32)
{
    int t = blockIdx.x;
    // piggyback: zero expert counters before the (later) gate_k launch
    if (o32 && t == 0 && threadIdx.x < NEXP) d_cnt[threadIdx.x] = 0;
    const float* xr = x + (long)t * NHID;
    __shared__ float red[256];
    float s = 0.f;
    for (int i = threadIdx.x; i < NHID; i += 256) { float v = xr[i]; s += v * v; }
    red[threadIdx.x] = s;
    __syncthreads();
    for (int st = 128; st > 0; st >>= 1) {
        if (threadIdx.x < st) red[threadIdx.x] += red[threadIdx.x + st];
        __syncthreads();
    }
    float scale = rsqrtf(red[0] / (float)NHID + 1e-6f);
    for (int i = threadIdx.x; i < NHID; i += 256) {
        float v = xr[i] * scale * w[i];
        oh[(long)t * NHID + i] = __float2half_rn(v);
        if (o32) o32[(long)t * NHID + i] = v;
    }
}

__global__ void rope_k(const __half* __restrict__ q0, const __half* __restrict__ k0,
                       const float* __restrict__ cosp, const float* __restrict__ sinp,
                       __half* __restrict__ qr, __half* __restrict__ kr)
{
    int t = blockIdx.x;
    int s = t % NS;
    const float inv = 0.08838834764831845f;  // 1/sqrt(128)
    for (int i = threadIdx.x; i < NHEAD * 64; i += 256) {
        int n = i >> 6, d = i & 63;
        long base = (long)t * NHID + n * DHEAD;
        float c  = cosp[s * DHEAD + d];
        float sn = sinp[s * DHEAD + d];
        float a0 = __half2float(q0[base + d]);
        float a1 = __half2float(q0[base + d + 64]);
        qr[base + d]      = __float2half_rn((a0 * c - a1 * sn) * inv);
        qr[base + d + 64] = __float2half_rn((a1 * c + a0 * sn) * inv);
        float b0 = __half2float(k0[base + d]);
        float b1 = __half2float(k0[base + d + 64]);
        kr[base + d]      = __float2half_rn(b0 * c - b1 * sn);
        kr[base + d + 64] = __float2half_rn(b1 * c + b0 * sn);
    }
}

__global__ void gate_k(const float* __restrict__ xn, const float* __restrict__ gw)
{
    int t = blockIdx.x;
    int tid = threadIdx.x, w = tid >> 5, lane = tid & 31;
    const float* xr = xn + (long)t * NHID;
    const float* gr = gw + (long)w * NHID;
    float s = 0.f;
    for (int i = lane; i < NHID; i += 32) s += xr[i] * gr[i];
    for (int o = 16; o; o >>= 1) s += __shfl_xor_sync(0xffffffffu, s, o);
    __shared__ float lg[NEXP];
    if (lane == 0) lg[w] = s;
    __syncthreads();
    if (tid == 0) {
        float mx = lg[0];
        for (int e = 1; e < NEXP; ++e) mx = fmaxf(mx, lg[e]);
        float p[NEXP];
        for (int e = 0; e < NEXP; ++e) p[e] = expf(lg[e] - mx);
        int e0 = 0; float b0 = p[0];
        for (int e = 1; e < NEXP; ++e) if (p[e] > b0) { b0 = p[e]; e0 = e; }
        int e1 = -1; float b1 = -1.f;
        for (int e = 0; e < NEXP; ++e)
            if (e != e0 && p[e] > b1) { b1 = p[e]; e1 = e; }
        float denom = b0 + b1;
        d_e0[t] = e0; d_e1[t] = e1;
        d_w0[t] = b0 / denom; d_w1[t] = b1 / denom;
        d_r0[t] = atomicAdd(&d_cnt[e0], 1);
        d_r1[t] = atomicAdd(&d_cnt[e1], 1);
    }
}

__global__ void scan_k()
{
    if (threadIdx.x == 0) {
        int a = 0;
        for (int e = 0; e < NEXP; ++e) { d_off[e] = a; a += d_cnt[e]; }
    }
}

__global__ void gather_k(const __half* __restrict__ xnh)
{
    int t = blockIdx.x;
    __shared__ int ss[2];
    if (threadIdx.x == 0) {
        int s0 = d_off[d_e0[t]] + d_r0[t];
        int s1 = d_off[d_e1[t]] + d_r1[t];
        d_s0[t] = s0; d_s1[t] = s1;
        ss[0] = s0; ss[1] = s1;
    }
    __syncthreads();
    const uint4* src = (const uint4*)(xnh + (long)t * NHID);
    uint4* dst0 = (uint4*)(h_xg + (long)ss[0] * NHID);
    uint4* dst1 = (uint4*)(h_xg + (long)ss[1] * NHID);
    for (int i = threadIdx.x; i < NHID / 8; i += 256) {
        uint4 v = src[i];
        dst0[i] = v;
        dst1[i] = v;
    }
}

// silu(g)*u, half in / half out, vectorized __half2
__global__ void silumul_k(const __half* __restrict__ g, const __half* __restrict__ u,
                          __half* __restrict__ o, long n2)
{
    long i = (long)blockIdx.x * 256 + threadIdx.x;
    if (i < n2) {
        __half2 gh = ((const __half2*)g)[i];
        __half2 uh = ((const __half2*)u)[i];
        float g0 = __low2float(gh),  g1 = __high2float(gh);
        float u0 = __low2float(uh),  u1 = __high2float(uh);
        float r0 = g0 / (1.f + __expf(-g0)) * u0;
        float r1 = g1 / (1.f + __expf(-g1)) * u1;
        ((__half2*)o)[i] = __floats2half2_rn(r0, r1);
    }
}

// out = x1 + sh + w0*yb[s0] + w1*yb[s1]  (yb half)
__global__ void combine_k(const float* __restrict__ x1,
                          const float* __restrict__ sh,
                          float* __restrict__ out)
{
    int t = blockIdx.x;
    float w0 = d_w0[t], w1 = d_w1[t];
    long o0 = (long)d_s0[t] * NHID;
    long o1 = (long)d_s1[t] * NHID;
    for (int i = threadIdx.x; i < NHID; i += 256) {
        long idx = (long)t * NHID + i;
        out[idx] = x1[idx] + sh[idx]
                 + w0 * __half2float(h_ybuf[o0 + i])
                 + w1 * __half2float(h_ybuf[o1 + i]);
    }
}

// ---------------------------------------------------------------------------
// Launch
// ---------------------------------------------------------------------------
extern "C" void kernel_launch(void* const* d_in, const int* in_sizes, int n_in,
                              void* d_out, int out_size)
{
    (void)in_sizes; (void)n_in; (void)out_size;

    const float* hs   = (const float*)d_in[0];
    const float* ln1  = (const float*)d_in[1];
    const float* ln2  = (const float*)d_in[2];
    const float* q_w  = (const float*)d_in[3];
    const float* k_w  = (const float*)d_in[4];
    const float* v_w  = (const float*)d_in[5];
    const float* o_w  = (const float*)d_in[6];
    const float* cosp = (const float*)d_in[7];
    const float* sinp = (const float*)d_in[8];
    const float* gate = (const float*)d_in[9];
    const float* eg   = (const float*)d_in[10];
    const float* eu   = (const float*)d_in[11];
    const float* ed   = (const float*)d_in[12];
    const float* sg   = (const float*)d_in[13];
    const float* su   = (const float*)d_in[14];
    const float* sd   = (const float*)d_in[15];
    float* out = (float*)d_out;

    float *xn32, *x1, *sh;
    __half *hxn, *hq0, *hk0, *hv0, *hqr, *hkr, *hctx, *hxg;
    __half *hg, *hu, *hgb, *hgs32, *hus32, *hgs, *how2, *hsd2;
    cudaGetSymbolAddress((void**)&xn32, d_xn32);
    cudaGetSymbolAddress((void**)&x1,  d_x1);
    cudaGetSymbolAddress((void**)&sh,  d_sh);
    cudaGetSymbolAddress((void**)&hxn, h_xn);
    cudaGetSymbolAddress((void**)&hq0, h_q0);
    cudaGetSymbolAddress((void**)&hk0, h_k0);
    cudaGetSymbolAddress((void**)&hv0, h_v0);
    cudaGetSymbolAddress((void**)&hqr, h_qr);
    cudaGetSymbolAddress((void**)&hkr, h_kr);
    cudaGetSymbolAddress((void**)&hctx, h_ctx);
    cudaGetSymbolAddress((void**)&hxg, h_xg);
    cudaGetSymbolAddress((void**)&hg,  h_gbuf);
    cudaGetSymbolAddress((void**)&hu,  h_ubuf);
    cudaGetSymbolAddress((void**)&hgb, h_gb);
    cudaGetSymbolAddress((void**)&hgs32, h_gs32);
    cudaGetSymbolAddress((void**)&hus32, h_us32);
    cudaGetSymbolAddress((void**)&hgs, h_gs);
    cudaGetSymbolAddress((void**)&how2, h_ow);
    cudaGetSymbolAddress((void**)&hsd2, h_sd);

    cudaFuncSetAttribute(hgemm_bat,
        cudaFuncAttributeMaxDynamicSharedMemorySize, SMEM_BYTES);
    cudaFuncSetAttribute(hqkv_k,
        cudaFuncAttributeMaxDynamicSharedMemorySize, SMEM_BYTES);
    cudaFuncSetAttribute(hshup_k,
        cudaFuncAttributeMaxDynamicSharedMemorySize, SMEM_BYTES);
    cudaFuncSetAttribute(hmoeup_k,
        cudaFuncAttributeMaxDynamicSharedMemorySize, SMEM_BYTES);
    cudaFuncSetAttribute(hmoedn_k,
        cudaFuncAttributeMaxDynamicSharedMemorySize, SMEM_BYTES);
    cudaFuncSetAttribute(flash_k,
        cudaFuncAttributeMaxDynamicSharedMemorySize, FLASH_SMEM);

    // ---- all weight conversions in one launch ----
    conv_all_k<<<(CONV_TOT + 255) / 256, 256>>>(q_w, k_w, v_w, o_w,
                                                eg, eu, ed, sg, su, sd);

    const dim3 gQKV(NHID / BN, NT / BM, 3);
    const dim3 gFlash(NS / 128, NB * NHEAD);
    const dim3 gProj(NHID / BN, NT / BM);
    const dim3 gShUp(NSI / BN, NT / BM, 2);
    const dim3 gMoeUp(NMI / BN, NSLOT / BM, 2 * NEXP);
    const dim3 gMoeDn(NHID / BN, NSLOT / BM, NEXP);

    // ---- attention ----
    rmsnorm_k<<<NT, 256>>>(hs, ln1, hxn, nullptr);
    hqkv_k<<<gQKV, 256, SMEM_BYTES>>>(hxn);
    rope_k<<<NT, 256>>>(hq0, hk0, cosp, sinp, hqr, hkr);
    flash_k<<<gFlash, 256, FLASH_SMEM>>>(hqr, hkr, hv0, hctx);
    hgemm_bat<<<gProj, 256, SMEM_BYTES>>>(hctx, how2, x1, hs,
        NT, NHID, NHID, NHID, NHID, 0, 0, 0);

    // ---- MoE ----
    rmsnorm_k<<<NT, 256>>>(x1, ln2, hxn, xn32);   // also zeroes d_cnt
    gate_k<<<NT, 256>>>(xn32, gate);
    scan_k<<<1, 1>>>();
    gather_k<<<NT, 256>>>(hxn);

    hmoeup_k<<<gMoeUp, 256, SMEM_BYTES>>>(hxg);
    silumul_k<<<(unsigned)(((long)NSLOT * NMI / 2 + 255) / 256), 256>>>(
        hg, hu, hgb, (long)NSLOT * NMI / 2);
    hmoedn_k<<<gMoeDn, 256, SMEM_BYTES>>>(hgb);

    // ---- shared MLP ----
    hshup_k<<<gShUp, 256, SMEM_BYTES>>>(hxn);
    silumul_k<<<(unsigned)(((long)NT * NSI / 2 + 255) / 256), 256>>>(
        hgs32, hus32, hgs, (long)NT * NSI / 2);
    hgemm_bat<<<gProj, 256, SMEM_BYTES>>>(hgs, hsd2, sh, nullptr,
        NT, NSI, NSI, NSI, NHID, 0, 0, 0);

    // ---- combine ----
    combine_k<<<NT, 256>>>(x1, sh, out);
}